// round 13
// baseline (speedup 1.0000x reference)
#include <cuda_runtime.h>
#include <cuda_bf16.h>
#include <math.h>
#include <stdint.h>

#define B_SZ   2048
#define K_OBJ  16
#define ROWS   (B_SZ * K_OBJ)      // 32768
#define NPAIR  120

typedef __nv_bfloat16 bf16;

// ---------------- scratch (device globals; no allocation allowed) ----------------
__device__ __align__(16) bf16 g_z_hi  [(size_t)ROWS * 128];
__device__ __align__(16) bf16 g_z_lo  [(size_t)ROWS * 128];
__device__ __align__(16) bf16 g_h0_hi [(size_t)ROWS * 128];
__device__ __align__(16) bf16 g_h0_lo [(size_t)ROWS * 128];
__device__ __align__(16) bf16 g_ze_hi [(size_t)ROWS * 256];
__device__ __align__(16) bf16 g_ze_lo [(size_t)ROWS * 256];
__device__ __align__(16) bf16 g_h_hi  [(size_t)ROWS * 128];
__device__ __align__(16) bf16 g_h_lo  [(size_t)ROWS * 128];
__device__ __align__(16) bf16 g_E_hi  [(size_t)ROWS * 512];
__device__ __align__(16) bf16 g_E_lo  [(size_t)ROWS * 512];
__device__ __align__(16) bf16 g_rel_hi[(size_t)ROWS * 128];
__device__ __align__(16) bf16 g_rel_lo[(size_t)ROWS * 128];
__device__ __align__(16) float g_gi [(size_t)ROWS * 384];
__device__ __align__(16) float g_gh [(size_t)ROWS * 384];
__device__ __align__(16) float g_UV [(size_t)ROWS * 1024];
__device__ __align__(16) bf16 g_Wobj_hi[256 * 128],  g_Wobj_lo[256 * 128];
__device__ __align__(16) bf16 g_Wih_hi [384 * 256],  g_Wih_lo [384 * 256];
__device__ __align__(16) bf16 g_Whh_hi [384 * 128],  g_Whh_lo [384 * 128];
__device__ __align__(16) bf16 g_WUV_hi [1024 * 128], g_WUV_lo [1024 * 128];
__device__ __align__(16) bf16 g_WcE_hi [128 * 640],  g_WcE_lo [128 * 640];
__device__ __align__(16) bf16 g_Wstk_hi[384 * 128],  g_Wstk_lo[384 * 128];
__device__ __align__(16) float g_bstk[384];

// ---------------- helpers ----------------
__device__ __forceinline__ void bf16split(float x, bf16& h, bf16& l) {
    h = __float2bfloat16_rn(x);
    l = __float2bfloat16_rn(x - __bfloat162float(h));
}

__device__ __forceinline__ uint32_t smem_u32(const void* p) {
    uint32_t a;
    asm("{ .reg .u64 t; cvta.to.shared.u64 t, %1; cvt.u32.u64 %0, t; }" : "=r"(a) : "l"(p));
    return a;
}

__device__ __forceinline__ void cp16(uint32_t dst, const void* src) {
    asm volatile("cp.async.ca.shared.global [%0], [%1], 16;" :: "r"(dst), "l"(src) : "memory");
}
#define CP_COMMIT() asm volatile("cp.async.commit_group;" ::: "memory")
#define CP_WAIT(n)  asm volatile("cp.async.wait_group %0;" :: "n"(n) : "memory")

__device__ __forceinline__ void mma16(float* d, const uint32_t* a, const uint32_t* b) {
    asm volatile(
        "mma.sync.aligned.m16n8k16.row.col.f32.bf16.bf16.f32 "
        "{%0,%1,%2,%3}, {%4,%5,%6,%7}, {%8,%9}, {%0,%1,%2,%3};"
        : "+f"(d[0]), "+f"(d[1]), "+f"(d[2]), "+f"(d[3])
        : "r"(a[0]), "r"(a[1]), "r"(a[2]), "r"(a[3]), "r"(b[0]), "r"(b[1]));
}

// ---------------- tensor-core bf16x3 NT GEMM, CTA 128x128, warp 32x64 ----------------
// Single barrier per K-slab (2-stage ring; passing iter-i barrier implies all
// warps finished iter i-1 MMAs, so overwriting stage (i+1)&1 is safe).
// Smem traffic per unit MMA work: 64 KB (vs 94 KB for 128x64 tile).
#define PADW 20
#define A_TW  2560   // 128 * PADW
#define STG_WORDS 10240   // 4 tiles * A_TW
#define STG_BYTES (STG_WORDS * 4)

template <int ACT, int OUTM>
__global__ void __launch_bounds__(256, 2) gemm_mma(
    const bf16* __restrict__ X1hi, const bf16* __restrict__ X1lo, int ld1, int k1,
    const bf16* __restrict__ X2hi, const bf16* __restrict__ X2lo, int ld2,
    const bf16* __restrict__ Whi, const bf16* __restrict__ Wlo,
    const float* __restrict__ bias,
    float* __restrict__ C, bf16* __restrict__ Chi, bf16* __restrict__ Clo,
    int ldc, float* __restrict__ C2, int Kd)
{
    extern __shared__ uint32_t smw[];
    const uint32_t sb = smem_u32(smw);

    const int tid = threadIdx.x;
    const int lane = tid & 31;
    const int wid = tid >> 5;
    const int warp_m = wid >> 1;       // 0..3
    const int warp_n = wid & 1;        // 0..1
    const int gid = lane >> 2;
    const int tig = lane & 3;
    const int bm = blockIdx.y * 128;
    const int bn = blockIdx.x * 128;

    float acc[2][8][4];
#pragma unroll
    for (int mi = 0; mi < 2; mi++)
#pragma unroll
        for (int nf = 0; nf < 8; nf++)
#pragma unroll
            for (int e = 0; e < 4; e++) acc[mi][nf][e] = 0.f;

    const int lrow = tid >> 1;
    const int lch2 = (tid & 1) * 2;

    auto load_slab = [&](int k0, int s) {
        const bf16 *ahi, *alo; int xld, xc;
        if (k0 < k1) { ahi = X1hi; alo = X1lo; xld = ld1; xc = k0; }
        else         { ahi = X2hi; alo = X2lo; xld = ld2; xc = k0 - k1; }
        const uint32_t st = sb + s * STG_BYTES;
#pragma unroll
        for (int c = 0; c < 2; c++) {
            int ch = lch2 + c;
            uint32_t so = (uint32_t)(lrow * PADW + ch * 4) * 4;
            const size_t ga = (size_t)(bm + lrow) * xld + xc + ch * 8;
            const size_t gw = (size_t)(bn + lrow) * Kd + k0 + ch * 8;
            cp16(st + so,                  ahi + ga);
            cp16(st + A_TW * 4 + so,       alo + ga);
            cp16(st + 2 * A_TW * 4 + so,   Whi + gw);
            cp16(st + 3 * A_TW * 4 + so,   Wlo + gw);
        }
    };

    load_slab(0, 0);
    CP_COMMIT();

    const int nIter = Kd >> 5;
#pragma unroll 1
    for (int i = 0; i < nIter; i++) {
        CP_WAIT(0);
        __syncthreads();
        if (i + 1 < nIter) {
            load_slab((i + 1) * 32, (i + 1) & 1);
            CP_COMMIT();
        }

        const uint32_t* sA  = smw + (i & 1) * STG_WORDS;
        const uint32_t* sAl = sA + A_TW;
        const uint32_t* sB  = sA + 2 * A_TW;
        const uint32_t* sBl = sA + 3 * A_TW;

#pragma unroll
        for (int h = 0; h < 2; h++) {
            const int kb = h * 8 + tig;
            uint32_t ah[2][4], al[2][4];
#pragma unroll
            for (int mi = 0; mi < 2; mi++) {
                int am = (warp_m * 32 + mi * 16 + gid) * PADW;
                ah[mi][0] = sA [am + kb];
                ah[mi][1] = sA [am + 8 * PADW + kb];
                ah[mi][2] = sA [am + kb + 4];
                ah[mi][3] = sA [am + 8 * PADW + kb + 4];
                al[mi][0] = sAl[am + kb];
                al[mi][1] = sAl[am + 8 * PADW + kb];
                al[mi][2] = sAl[am + kb + 4];
                al[mi][3] = sAl[am + 8 * PADW + kb + 4];
            }
            uint32_t bf[8][2];
#pragma unroll
            for (int nf = 0; nf < 8; nf++) {
                int an = (warp_n * 64 + nf * 8 + gid) * PADW;
                bf[nf][0] = sB[an + kb];
                bf[nf][1] = sB[an + kb + 4];
            }
#pragma unroll
            for (int mi = 0; mi < 2; mi++)
#pragma unroll
                for (int nf = 0; nf < 8; nf++)
                    mma16(acc[mi][nf], ah[mi], bf[nf]);
#pragma unroll
            for (int mi = 0; mi < 2; mi++)
#pragma unroll
                for (int nf = 0; nf < 8; nf++)
                    mma16(acc[mi][nf], al[mi], bf[nf]);
#pragma unroll
            for (int nf = 0; nf < 8; nf++) {
                int an = (warp_n * 64 + nf * 8 + gid) * PADW;
                bf[nf][0] = sBl[an + kb];
                bf[nf][1] = sBl[an + kb + 4];
            }
#pragma unroll
            for (int mi = 0; mi < 2; mi++)
#pragma unroll
                for (int nf = 0; nf < 8; nf++)
                    mma16(acc[mi][nf], ah[mi], bf[nf]);
        }
    }

    // ---- epilogue ----
    float* outp = C; int oldc = ldc, ncol0 = bn;
    if (OUTM == 2) {
        if (bn >= 256) { outp = C2; oldc = 128; ncol0 = bn - 256; }
        else           { outp = C;  oldc = 256; ncol0 = bn; }
    }

#pragma unroll
    for (int mi = 0; mi < 2; mi++) {
        int r0 = bm + warp_m * 32 + mi * 16 + gid;
#pragma unroll
        for (int nf = 0; nf < 8; nf++) {
            int cg = bn + warp_n * 64 + nf * 8 + tig * 2;
            int cl = ncol0 + warp_n * 64 + nf * 8 + tig * 2;
            float b0 = 0.f, b1 = 0.f;
            if (bias) { float2 bv = *(const float2*)(bias + cg); b0 = bv.x; b1 = bv.y; }
            float v00 = acc[mi][nf][0] + b0;
            float v01 = acc[mi][nf][1] + b1;
            float v10 = acc[mi][nf][2] + b0;
            float v11 = acc[mi][nf][3] + b1;
            if (ACT == 1) {
                v00 = (v00 > 0.f) ? v00 : (__expf(v00) - 1.f);
                v01 = (v01 > 0.f) ? v01 : (__expf(v01) - 1.f);
                v10 = (v10 > 0.f) ? v10 : (__expf(v10) - 1.f);
                v11 = (v11 > 0.f) ? v11 : (__expf(v11) - 1.f);
            }
            if (OUTM == 1) {
                bf16 h, l;
                __nv_bfloat162 ph0, pl0, ph1, pl1;
                bf16split(v00, h, l); ph0.x = h; pl0.x = l;
                bf16split(v01, h, l); ph0.y = h; pl0.y = l;
                bf16split(v10, h, l); ph1.x = h; pl1.x = l;
                bf16split(v11, h, l); ph1.y = h; pl1.y = l;
                *(__nv_bfloat162*)(Chi + (size_t)r0 * ldc + cl)       = ph0;
                *(__nv_bfloat162*)(Clo + (size_t)r0 * ldc + cl)       = pl0;
                *(__nv_bfloat162*)(Chi + (size_t)(r0 + 8) * ldc + cl) = ph1;
                *(__nv_bfloat162*)(Clo + (size_t)(r0 + 8) * ldc + cl) = pl1;
            } else {
                *(float2*)(outp + (size_t)r0 * oldc + cl)       = make_float2(v00, v01);
                *(float2*)(outp + (size_t)(r0 + 8) * oldc + cl) = make_float2(v10, v11);
            }
        }
    }
}

// ---------------- merged split kernel (z, h0, W_obj, Wih, Whh) ----------------
#define N4_Z   1048576
#define N4_H0  1048576
#define N4_WO  8192
#define N4_WIH 24576
#define N4_WHH 12288
#define N4_TOT (N4_Z + N4_H0 + N4_WO + N4_WIH + N4_WHH)

__device__ __forceinline__ void split4(const float4* src, bf16* hi, bf16* lo, int i) {
    float4 v = src[i];
    bf16 h, l;
    __nv_bfloat162 h0, l0, h1, l1;
    bf16split(v.x, h, l); h0.x = h; l0.x = l;
    bf16split(v.y, h, l); h0.y = h; l0.y = l;
    bf16split(v.z, h, l); h1.x = h; l1.x = l;
    bf16split(v.w, h, l); h1.y = h; l1.y = l;
    ((__nv_bfloat162*)hi)[i * 2]     = h0; ((__nv_bfloat162*)lo)[i * 2]     = l0;
    ((__nv_bfloat162*)hi)[i * 2 + 1] = h1; ((__nv_bfloat162*)lo)[i * 2 + 1] = l1;
}

__global__ void split_all(const float* __restrict__ z, const float* __restrict__ h0,
                          const float* __restrict__ W_obj, const float* __restrict__ Wih,
                          const float* __restrict__ Whh) {
    int idx = blockIdx.x * blockDim.x + threadIdx.x;
    if (idx >= N4_TOT) return;
    if (idx < N4_Z) {
        split4((const float4*)z, g_z_hi, g_z_lo, idx);
    } else if ((idx -= N4_Z) < N4_H0) {
        split4((const float4*)h0, g_h0_hi, g_h0_lo, idx);
    } else if ((idx -= N4_H0) < N4_WO) {
        split4((const float4*)W_obj, g_Wobj_hi, g_Wobj_lo, idx);
    } else if ((idx -= N4_WO) < N4_WIH) {
        split4((const float4*)Wih, g_Wih_hi, g_Wih_lo, idx);
    } else {
        idx -= N4_WIH;
        split4((const float4*)Whh, g_Whh_hi, g_Whh_lo, idx);
    }
}

// ---------------- merged weight-fold kernel (WUV, WcE, Wstk, bstk) ----------------
#define N_WUV  131072
#define N_WCE  81920
#define N_WSTK 49152
#define N_PREP (N_WUV + N_WCE + N_WSTK + 384)

__global__ void prep_all(const float* __restrict__ We, const float* __restrict__ Wc,
                         const float* __restrict__ Wl, const float* __restrict__ bl,
                         const float* __restrict__ Wsc, const float* __restrict__ bs,
                         const float* __restrict__ Wh, const float* __restrict__ bh) {
    int idx = blockIdx.x * blockDim.x + threadIdx.x;
    if (idx >= N_PREP) return;
    if (idx < N_WUV) {
        int n = idx >> 7, c = idx & 127;
        float v;
        if (n < 512) v = We[n * 512 + c] + We[n * 512 + 128 + c];
        else {
            int nn = n - 512;
            v = We[nn * 512 + 256 + c] + We[nn * 512 + 384 + c];
        }
        bf16 h, l; bf16split(v, h, l);
        g_WUV_hi[idx] = h; g_WUV_lo[idx] = l;
    } else if ((idx -= N_WUV) < N_WCE) {
        int n = idx / 640, c = idx % 640;
        float v = (c < 128) ? (Wc[n * 768 + c] + Wc[n * 768 + 128 + c])
                            : Wc[n * 768 + 128 + c];
        bf16 h, l; bf16split(v, h, l);
        g_WcE_hi[idx] = h; g_WcE_lo[idx] = l;
    } else if ((idx -= N_WCE) < N_WSTK) {
        int n = idx >> 7, c = idx & 127;
        const float* W = (n < 128) ? Wl : ((n < 256) ? Wsc : Wh);
        bf16 h, l; bf16split(W[(n & 127) * 128 + c], h, l);
        g_Wstk_hi[idx] = h; g_Wstk_lo[idx] = l;
    } else {
        idx -= N_WSTK;
        const float* bb = (idx < 128) ? bl : ((idx < 256) ? bs : bh);
        g_bstk[idx] = bb[idx & 127];
    }
}

// ---------------- GRU gate fusion (float4 vectorized, writes split h) ----------------
__device__ __forceinline__ float sigm(float x) { return 1.f / (1.f + __expf(-x)); }

__global__ void gru_gate(const float* __restrict__ gi, const float* __restrict__ gh,
                         const float* __restrict__ h0,
                         bf16* __restrict__ hhi, bf16* __restrict__ hlo) {
    int idx = blockIdx.x * blockDim.x + threadIdx.x;
    if (idx >= ROWS * 32) return;
    int m = idx >> 5, c4 = (idx & 31) * 4;
    const float* gim = gi + (size_t)m * 384;
    const float* ghm = gh + (size_t)m * 384;
    float4 gir = *(const float4*)(gim + c4);
    float4 giu = *(const float4*)(gim + 128 + c4);
    float4 gin = *(const float4*)(gim + 256 + c4);
    float4 ghr = *(const float4*)(ghm + c4);
    float4 ghu = *(const float4*)(ghm + 128 + c4);
    float4 ghn = *(const float4*)(ghm + 256 + c4);
    float4 h0v = *(const float4*)(h0 + (size_t)m * 128 + c4);
    float out[4];
    {
        float r = sigm(gir.x + ghr.x), u = sigm(giu.x + ghu.x);
        out[0] = (1.f - u) * tanhf(gin.x + r * ghn.x) + u * h0v.x;
        r = sigm(gir.y + ghr.y); u = sigm(giu.y + ghu.y);
        out[1] = (1.f - u) * tanhf(gin.y + r * ghn.y) + u * h0v.y;
        r = sigm(gir.z + ghr.z); u = sigm(giu.z + ghu.z);
        out[2] = (1.f - u) * tanhf(gin.z + r * ghn.z) + u * h0v.z;
        r = sigm(gir.w + ghr.w); u = sigm(giu.w + ghu.w);
        out[3] = (1.f - u) * tanhf(gin.w + r * ghn.w) + u * h0v.w;
    }
    __nv_bfloat162 ph0, pl0, ph1, pl1;
    bf16 h, l;
    bf16split(out[0], h, l); ph0.x = h; pl0.x = l;
    bf16split(out[1], h, l); ph0.y = h; pl0.y = l;
    bf16split(out[2], h, l); ph1.x = h; pl1.x = l;
    bf16split(out[3], h, l); ph1.y = h; pl1.y = l;
    __nv_bfloat162* ho = (__nv_bfloat162*)(hhi + (size_t)m * 128 + c4);
    __nv_bfloat162* lo2 = (__nv_bfloat162*)(hlo + (size_t)m * 128 + c4);
    ho[0] = ph0; ho[1] = ph1;
    lo2[0] = pl0; lo2[1] = pl1;
}

// ---------------- pair stage: warp-per-object, atomic-free ----------------
__global__ void __launch_bounds__(512) pair_kernel(
    const float* __restrict__ UV, const float* __restrict__ Wa,
    const float* __restrict__ ba, const float* __restrict__ be,
    bf16* __restrict__ Ehi, bf16* __restrict__ Elo)
{
    extern __shared__ float smf[];
    float* Ub = smf;
    float* Vb = Ub + 16 * 512;

    const int b = blockIdx.x;
    const int tid = threadIdx.x;
    const int w = tid >> 5, lane = tid & 31;

    for (int i = tid; i < 16 * 512; i += 512) {
        int k = i >> 9, t = i & 511;
        const float* row = UV + (size_t)(b * 16 + k) * 1024;
        Ub[i] = row[t];
        Vb[i] = row[512 + t];
    }
    __syncthreads();

    const float ba0 = __ldg(&ba[0]);
    float uw[16], vw[16], ber[16], war[16], Ew[16];
#pragma unroll
    for (int c = 0; c < 16; c++) {
        int t = lane + 32 * c;
        uw[c] = Ub[w * 512 + t];
        vw[c] = Vb[w * 512 + t];
        ber[c] = __ldg(&be[t]);
        war[c] = __ldg(&Wa[t]);
        Ew[c] = 0.f;
    }

#pragma unroll 1
    for (int o = 0; o < K_OBJ; o++) {
        if (o == w) continue;
        const float* Urow = Ub + o * 512;
        const float* Vrow = Vb + o * 512;
        float e[16];
        float dot = 0.f;
        if (o > w) {
#pragma unroll
            for (int c = 0; c < 16; c++) {
                float x = uw[c] + Vrow[lane + 32 * c] + ber[c];
                x = (x > 0.f) ? x : (__expf(x) - 1.f);
                e[c] = x;
                dot += x * war[c];
            }
        } else {
#pragma unroll
            for (int c = 0; c < 16; c++) {
                float x = Urow[lane + 32 * c] + vw[c] + ber[c];
                x = (x > 0.f) ? x : (__expf(x) - 1.f);
                e[c] = x;
                dot += x * war[c];
            }
        }
#pragma unroll
        for (int off = 16; off > 0; off >>= 1) dot += __shfl_xor_sync(0xffffffffu, dot, off);
        float att = 1.f / (1.f + __expf(-(dot + ba0)));
#pragma unroll
        for (int c = 0; c < 16; c++) Ew[c] += att * e[c];
    }

    bf16* Eh = Ehi + ((size_t)b * 16 + w) * 512;
    bf16* El = Elo + ((size_t)b * 16 + w) * 512;
#pragma unroll
    for (int c = 0; c < 16; c++) {
        bf16 h, l; bf16split(Ew[c], h, l);
        Eh[lane + 32 * c] = h;
        El[lane + 32 * c] = l;
    }
}

// ---------------- host launcher ----------------
extern "C" void kernel_launch(void* const* d_in, const int* in_sizes, int n_in,
                              void* d_out, int out_size)
{
    const float* z    = (const float*)d_in[0];
    const float* h0   = (const float*)d_in[1];
    const float* W_obj= (const float*)d_in[2];
    const float* b_obj= (const float*)d_in[3];
    const float* Wih  = (const float*)d_in[4];
    const float* bih  = (const float*)d_in[5];
    const float* Whh  = (const float*)d_in[6];
    const float* bhh  = (const float*)d_in[7];
    const float* We   = (const float*)d_in[8];
    const float* be   = (const float*)d_in[9];
    const float* Wa   = (const float*)d_in[10];
    const float* ba   = (const float*)d_in[11];
    const float* Wc   = (const float*)d_in[12];
    const float* bc   = (const float*)d_in[13];
    const float* Wl   = (const float*)d_in[14];
    const float* bl   = (const float*)d_in[15];
    const float* Wsc  = (const float*)d_in[16];
    const float* bs   = (const float*)d_in[17];
    const float* Wh   = (const float*)d_in[18];
    const float* bh   = (const float*)d_in[19];

    float* out1 = (float*)d_out;
    float* out2 = out1 + (size_t)ROWS * 256;

    bf16 *p_z_hi, *p_z_lo, *p_h0_hi, *p_h0_lo, *p_ze_hi, *p_ze_lo;
    bf16 *p_h_hi, *p_h_lo, *p_E_hi, *p_E_lo, *p_rel_hi, *p_rel_lo;
    float *p_gi, *p_gh, *p_UV, *p_bstk;
    bf16 *p_Wobj_hi, *p_Wobj_lo, *p_Wih_hi, *p_Wih_lo, *p_Whh_hi, *p_Whh_lo;
    bf16 *p_WUV_hi, *p_WUV_lo, *p_WcE_hi, *p_WcE_lo, *p_Wstk_hi, *p_Wstk_lo;

    cudaGetSymbolAddress((void**)&p_z_hi,  g_z_hi);   cudaGetSymbolAddress((void**)&p_z_lo,  g_z_lo);
    cudaGetSymbolAddress((void**)&p_h0_hi, g_h0_hi);  cudaGetSymbolAddress((void**)&p_h0_lo, g_h0_lo);
    cudaGetSymbolAddress((void**)&p_ze_hi, g_ze_hi);  cudaGetSymbolAddress((void**)&p_ze_lo, g_ze_lo);
    cudaGetSymbolAddress((void**)&p_h_hi,  g_h_hi);   cudaGetSymbolAddress((void**)&p_h_lo,  g_h_lo);
    cudaGetSymbolAddress((void**)&p_E_hi,  g_E_hi);   cudaGetSymbolAddress((void**)&p_E_lo,  g_E_lo);
    cudaGetSymbolAddress((void**)&p_rel_hi,g_rel_hi); cudaGetSymbolAddress((void**)&p_rel_lo,g_rel_lo);
    cudaGetSymbolAddress((void**)&p_gi, g_gi);
    cudaGetSymbolAddress((void**)&p_gh, g_gh);
    cudaGetSymbolAddress((void**)&p_UV, g_UV);
    cudaGetSymbolAddress((void**)&p_bstk, g_bstk);
    cudaGetSymbolAddress((void**)&p_Wobj_hi, g_Wobj_hi); cudaGetSymbolAddress((void**)&p_Wobj_lo, g_Wobj_lo);
    cudaGetSymbolAddress((void**)&p_Wih_hi,  g_Wih_hi);  cudaGetSymbolAddress((void**)&p_Wih_lo,  g_Wih_lo);
    cudaGetSymbolAddress((void**)&p_Whh_hi,  g_Whh_hi);  cudaGetSymbolAddress((void**)&p_Whh_lo,  g_Whh_lo);
    cudaGetSymbolAddress((void**)&p_WUV_hi,  g_WUV_hi);  cudaGetSymbolAddress((void**)&p_WUV_lo,  g_WUV_lo);
    cudaGetSymbolAddress((void**)&p_WcE_hi,  g_WcE_hi);  cudaGetSymbolAddress((void**)&p_WcE_lo,  g_WcE_lo);
    cudaGetSymbolAddress((void**)&p_Wstk_hi, g_Wstk_hi); cudaGetSymbolAddress((void**)&p_Wstk_lo, g_Wstk_lo);

    const int SMEM_GEMM = 2 * STG_BYTES;   // 81920
    cudaFuncSetAttribute(gemm_mma<1,1>, cudaFuncAttributeMaxDynamicSharedMemorySize, SMEM_GEMM);
    cudaFuncSetAttribute(gemm_mma<0,0>, cudaFuncAttributeMaxDynamicSharedMemorySize, SMEM_GEMM);
    cudaFuncSetAttribute(gemm_mma<0,1>, cudaFuncAttributeMaxDynamicSharedMemorySize, SMEM_GEMM);
    cudaFuncSetAttribute(gemm_mma<0,2>, cudaFuncAttributeMaxDynamicSharedMemorySize, SMEM_GEMM);

    split_all<<<(N4_TOT + 255) / 256, 256>>>(z, h0, W_obj, Wih, Whh);
    prep_all<<<(N_PREP + 255) / 256, 256>>>(We, Wc, Wl, bl, Wsc, bs, Wh, bh);

    const int MB = ROWS / 128;   // 256

    // G1: z_embed = elu(z @ W_obj^T + b_obj) -> split  [ROWS, 256]
    gemm_mma<1,1><<<dim3(2, MB), 256, SMEM_GEMM>>>(
        p_z_hi, p_z_lo, 128, 128, nullptr, nullptr, 0,
        p_Wobj_hi, p_Wobj_lo, b_obj, nullptr, p_ze_hi, p_ze_lo, 256, nullptr, 128);
    // G2a: gi = z_embed @ Wih^T + bih  [ROWS, 384] f32
    gemm_mma<0,0><<<dim3(3, MB), 256, SMEM_GEMM>>>(
        p_ze_hi, p_ze_lo, 256, 256, nullptr, nullptr, 0,
        p_Wih_hi, p_Wih_lo, bih, p_gi, nullptr, nullptr, 384, nullptr, 256);
    // G2b: gh = h0 @ Whh^T + bhh  [ROWS, 384] f32
    gemm_mma<0,0><<<dim3(3, MB), 256, SMEM_GEMM>>>(
        p_h0_hi, p_h0_lo, 128, 128, nullptr, nullptr, 0,
        p_Whh_hi, p_Whh_lo, bhh, p_gh, nullptr, nullptr, 384, nullptr, 128);
    // GRU gates -> h (split)
    gru_gate<<<(ROWS * 32 + 255) / 256, 256>>>(p_gi, p_gh, h0, p_h_hi, p_h_lo);

    // G3: UV = h @ W_UV^T  [ROWS, 1024] f32
    gemm_mma<0,0><<<dim3(8, MB), 256, SMEM_GEMM>>>(
        p_h_hi, p_h_lo, 128, 128, nullptr, nullptr, 0,
        p_WUV_hi, p_WUV_lo, nullptr, p_UV, nullptr, nullptr, 1024, nullptr, 128);

    // pair stage -> E (split) [ROWS, 512], atomic-free
    size_t psmem = (2 * 16 * 512) * sizeof(float);
    cudaFuncSetAttribute(pair_kernel, cudaFuncAttributeMaxDynamicSharedMemorySize, (int)psmem);
    pair_kernel<<<B_SZ, 512, psmem>>>(p_UV, Wa, ba, be, p_E_hi, p_E_lo);

    // G4: rel = [h | E] @ WcE^T + bc -> split  [ROWS, 128], Kd=640
    gemm_mma<0,1><<<dim3(1, MB), 256, SMEM_GEMM>>>(
        p_h_hi, p_h_lo, 128, 128, p_E_hi, p_E_lo, 512,
        p_WcE_hi, p_WcE_lo, bc, nullptr, p_rel_hi, p_rel_lo, 128, nullptr, 640);

    // G5: [loc|scale|h_out] = rel @ Wstk^T + bstk, final f32 split outputs
    gemm_mma<0,2><<<dim3(3, MB), 256, SMEM_GEMM>>>(
        p_rel_hi, p_rel_lo, 128, 128, nullptr, nullptr, 0,
        p_Wstk_hi, p_Wstk_lo, p_bstk, out1, nullptr, nullptr, 0, out2, 128);
}

// round 14
// speedup vs baseline: 1.0402x; 1.0402x over previous
#include <cuda_runtime.h>
#include <cuda_bf16.h>
#include <math.h>
#include <stdint.h>

#define B_SZ   2048
#define K_OBJ  16
#define ROWS   (B_SZ * K_OBJ)      // 32768
#define NPAIR  120

typedef __nv_bfloat16 bf16;

// ---------------- scratch (device globals; no allocation allowed) ----------------
__device__ __align__(16) bf16 g_z_hi  [(size_t)ROWS * 128];
__device__ __align__(16) bf16 g_z_lo  [(size_t)ROWS * 128];
__device__ __align__(16) bf16 g_h0_hi [(size_t)ROWS * 128];
__device__ __align__(16) bf16 g_h0_lo [(size_t)ROWS * 128];
__device__ __align__(16) bf16 g_ze_hi [(size_t)ROWS * 256];
__device__ __align__(16) bf16 g_ze_lo [(size_t)ROWS * 256];
__device__ __align__(16) bf16 g_h_hi  [(size_t)ROWS * 128];
__device__ __align__(16) bf16 g_h_lo  [(size_t)ROWS * 128];
__device__ __align__(16) bf16 g_E_hi  [(size_t)ROWS * 512];
__device__ __align__(16) bf16 g_E_lo  [(size_t)ROWS * 512];
__device__ __align__(16) bf16 g_rel_hi[(size_t)ROWS * 128];
__device__ __align__(16) bf16 g_rel_lo[(size_t)ROWS * 128];
__device__ __align__(16) float g_gi [(size_t)ROWS * 384];   // also G4 partial0 (ld128)
__device__ __align__(16) float g_gh [(size_t)ROWS * 384];   // also G4 partial1 (ld128)
__device__ __align__(16) float g_UV [(size_t)ROWS * 1024];
__device__ __align__(16) bf16 g_Wobj_hi[256 * 128],  g_Wobj_lo[256 * 128];
__device__ __align__(16) bf16 g_Wih_hi [384 * 256],  g_Wih_lo [384 * 256];
__device__ __align__(16) bf16 g_Whh_hi [384 * 128],  g_Whh_lo [384 * 128];
__device__ __align__(16) bf16 g_WUV_hi [1024 * 128], g_WUV_lo [1024 * 128];
__device__ __align__(16) bf16 g_WcE_hi [128 * 640],  g_WcE_lo [128 * 640];
__device__ __align__(16) bf16 g_Wstk_hi[384 * 128],  g_Wstk_lo[384 * 128];
__device__ __align__(16) float g_bstk[384];

// ---------------- helpers ----------------
__device__ __forceinline__ void bf16split(float x, bf16& h, bf16& l) {
    h = __float2bfloat16_rn(x);
    l = __float2bfloat16_rn(x - __bfloat162float(h));
}

__device__ __forceinline__ uint32_t smem_u32(const void* p) {
    uint32_t a;
    asm("{ .reg .u64 t; cvta.to.shared.u64 t, %1; cvt.u32.u64 %0, t; }" : "=r"(a) : "l"(p));
    return a;
}

__device__ __forceinline__ void cp16(uint32_t dst, const void* src) {
    asm volatile("cp.async.ca.shared.global [%0], [%1], 16;" :: "r"(dst), "l"(src) : "memory");
}
#define CP_COMMIT() asm volatile("cp.async.commit_group;" ::: "memory")
#define CP_WAIT(n)  asm volatile("cp.async.wait_group %0;" :: "n"(n) : "memory")

__device__ __forceinline__ void mma16(float* d, const uint32_t* a, const uint32_t* b) {
    asm volatile(
        "mma.sync.aligned.m16n8k16.row.col.f32.bf16.bf16.f32 "
        "{%0,%1,%2,%3}, {%4,%5,%6,%7}, {%8,%9}, {%0,%1,%2,%3};"
        : "+f"(d[0]), "+f"(d[1]), "+f"(d[2]), "+f"(d[3])
        : "r"(a[0]), "r"(a[1]), "r"(a[2]), "r"(a[3]), "r"(b[0]), "r"(b[1]));
}

// ---------------- tensor-core bf16x3 NT GEMM, CTA 128x64, 3 CTAs/SM (R12) ----------------
// OUTM: 0 f32 C; 1 bf16-split (Chi,Clo); 2 final f32 split (C ld256 / C2 ld128);
//       5 G4 split-K (grid.x packs 2 K-halves; raw f32 partials to g_gi/g_gh ld128);
//       6 merged G1(x<4: elu+split->Chi/Clo ld256) / G2b(x>=4: f32->g_gh ld384, bias=C2).
#define PADW 20
#define A_TW  2560   // 128 * PADW
#define B_TW  1280   //  64 * PADW
#define STG_WORDS 7680
#define STG_BYTES (STG_WORDS * 4)

template <int ACT, int OUTM>
__global__ void __launch_bounds__(256, 3) gemm_mma(
    const bf16* __restrict__ X1hi, const bf16* __restrict__ X1lo, int ld1, int k1,
    const bf16* __restrict__ X2hi, const bf16* __restrict__ X2lo, int ld2,
    const bf16* __restrict__ Whi, const bf16* __restrict__ Wlo,
    const float* __restrict__ bias,
    float* __restrict__ C, bf16* __restrict__ Chi, bf16* __restrict__ Clo,
    int ldc, float* __restrict__ C2, int Kd)
{
    extern __shared__ uint32_t smw[];
    const uint32_t sb = smem_u32(smw);

    const int tid = threadIdx.x;
    const int lane = tid & 31;
    const int wid = tid >> 5;
    const int warp_m = wid >> 1;
    const int warp_n = wid & 1;
    const int gid = lane >> 2;
    const int tig = lane & 3;
    const int bm = blockIdx.y * 128;

    // runtime operand selection (OUTM 5/6); defaults = params
    int bx = blockIdx.x;
    const bf16 *x1hi = X1hi, *x1lo = X1lo, *x2hi = X2hi, *x2lo = X2lo;
    const bf16 *whi = Whi, *wlo = Wlo;
    const float* biasp = bias;
    int l1 = ld1, l2 = ld2, kb1 = k1, wld = Kd, woff = 0;
    int subq = 0;
    if (OUTM == 5) {                 // Kd = 320 per half
        subq = bx >> 1; bx &= 1;
        wld = 640; biasp = nullptr;
        if (subq == 1) {
            x1hi = g_E_hi + 192; x1lo = g_E_lo + 192; l1 = 512; kb1 = 1 << 30;
            woff = 320;
        }
    }
    if (OUTM == 6) {                 // Kd = 128
        if (bx >= 4) {
            subq = 1; bx -= 4;
            x1hi = g_h0_hi; x1lo = g_h0_lo; l1 = 128; kb1 = 128;
            whi = g_Whh_hi; wlo = g_Whh_lo;
            biasp = (const float*)C2;   // bhh
        }
    }
    const int bn = bx * 64;

    float acc[2][4][4];
#pragma unroll
    for (int mi = 0; mi < 2; mi++)
#pragma unroll
        for (int nf = 0; nf < 4; nf++)
#pragma unroll
            for (int e = 0; e < 4; e++) acc[mi][nf][e] = 0.f;

    auto load_slab = [&](int k0, int s) {
        const bf16 *ahi, *alo; int xld, xc;
        if (k0 < kb1) { ahi = x1hi; alo = x1lo; xld = l1; xc = k0; }
        else          { ahi = x2hi; alo = x2lo; xld = l2; xc = k0 - kb1; }
        const uint32_t st = sb + s * STG_BYTES;
#pragma unroll
        for (int j = 0; j < 2; j++) {
            int c = tid + j * 256;
            int row = c >> 2, ch = c & 3;
            uint32_t so = (uint32_t)(row * PADW + ch * 4) * 4;
            const size_t ga = (size_t)(bm + row) * xld + xc + ch * 8;
            cp16(st + so,            ahi + ga);
            cp16(st + A_TW * 4 + so, alo + ga);
        }
        {
            int row = tid >> 2, ch = tid & 3;
            uint32_t so = (uint32_t)(row * PADW + ch * 4) * 4;
            const size_t gw = (size_t)(bn + row) * wld + woff + k0 + ch * 8;
            cp16(st + 2 * A_TW * 4 + so,          whi + gw);
            cp16(st + (2 * A_TW + B_TW) * 4 + so, wlo + gw);
        }
    };

    load_slab(0, 0);
    CP_COMMIT();

    const int nIter = Kd >> 5;
#pragma unroll 1
    for (int i = 0; i < nIter; i++) {
        CP_WAIT(0);
        __syncthreads();
        if (i + 1 < nIter) {
            load_slab((i + 1) * 32, (i + 1) & 1);
            CP_COMMIT();
        }

        const uint32_t* sA  = smw + (i & 1) * STG_WORDS;
        const uint32_t* sAl = sA + A_TW;
        const uint32_t* sB  = sA + 2 * A_TW;
        const uint32_t* sBl = sA + 2 * A_TW + B_TW;

#pragma unroll
        for (int h = 0; h < 2; h++) {
            const int kb = h * 8 + tig;
            uint32_t ah[2][4], al[2][4];
#pragma unroll
            for (int mi = 0; mi < 2; mi++) {
                int am = (warp_m * 32 + mi * 16 + gid) * PADW;
                ah[mi][0] = sA [am + kb];
                ah[mi][1] = sA [am + 8 * PADW + kb];
                ah[mi][2] = sA [am + kb + 4];
                ah[mi][3] = sA [am + 8 * PADW + kb + 4];
                al[mi][0] = sAl[am + kb];
                al[mi][1] = sAl[am + 8 * PADW + kb];
                al[mi][2] = sAl[am + kb + 4];
                al[mi][3] = sAl[am + 8 * PADW + kb + 4];
            }
            uint32_t bf[4][2];
#pragma unroll
            for (int nf = 0; nf < 4; nf++) {
                int an = (warp_n * 32 + nf * 8 + gid) * PADW;
                bf[nf][0] = sB[an + kb];
                bf[nf][1] = sB[an + kb + 4];
            }
#pragma unroll
            for (int mi = 0; mi < 2; mi++)
#pragma unroll
                for (int nf = 0; nf < 4; nf++)
                    mma16(acc[mi][nf], ah[mi], bf[nf]);
#pragma unroll
            for (int mi = 0; mi < 2; mi++)
#pragma unroll
                for (int nf = 0; nf < 4; nf++)
                    mma16(acc[mi][nf], al[mi], bf[nf]);
#pragma unroll
            for (int nf = 0; nf < 4; nf++) {
                int an = (warp_n * 32 + nf * 8 + gid) * PADW;
                bf[nf][0] = sBl[an + kb];
                bf[nf][1] = sBl[an + kb + 4];
            }
#pragma unroll
            for (int mi = 0; mi < 2; mi++)
#pragma unroll
                for (int nf = 0; nf < 4; nf++)
                    mma16(acc[mi][nf], ah[mi], bf[nf]);
        }
    }

    // ---- epilogue ----
    float* outp = C; int oldc = ldc, ncol0 = bn;
    bf16 *chip = Chi, *clop = Clo; int sldc = ldc;
    bool splitOut = (OUTM == 1);
    bool doElu = (ACT == 1);
    if (OUTM == 2) {
        if (bn >= 256) { outp = C2; oldc = 128; ncol0 = bn - 256; }
        else           { outp = C;  oldc = 256; ncol0 = bn; }
    }
    if (OUTM == 5) { outp = subq ? g_gh : g_gi; oldc = 128; ncol0 = bn; }
    if (OUTM == 6) {
        if (subq == 0) { splitOut = true; doElu = true; sldc = 256; }
        else           { outp = g_gh; oldc = 384; ncol0 = bn; }
    }

#pragma unroll
    for (int mi = 0; mi < 2; mi++) {
        int r0 = bm + warp_m * 32 + mi * 16 + gid;
#pragma unroll
        for (int nf = 0; nf < 4; nf++) {
            int cg = bn + warp_n * 32 + nf * 8 + tig * 2;
            int cl = ncol0 + warp_n * 32 + nf * 8 + tig * 2;
            float b0 = 0.f, b1 = 0.f;
            if (biasp) { float2 bv = *(const float2*)(biasp + cg); b0 = bv.x; b1 = bv.y; }
            float v00 = acc[mi][nf][0] + b0;
            float v01 = acc[mi][nf][1] + b1;
            float v10 = acc[mi][nf][2] + b0;
            float v11 = acc[mi][nf][3] + b1;
            if (doElu) {
                v00 = (v00 > 0.f) ? v00 : (__expf(v00) - 1.f);
                v01 = (v01 > 0.f) ? v01 : (__expf(v01) - 1.f);
                v10 = (v10 > 0.f) ? v10 : (__expf(v10) - 1.f);
                v11 = (v11 > 0.f) ? v11 : (__expf(v11) - 1.f);
            }
            if (splitOut) {
                bf16 h, l;
                __nv_bfloat162 ph0, pl0, ph1, pl1;
                bf16split(v00, h, l); ph0.x = h; pl0.x = l;
                bf16split(v01, h, l); ph0.y = h; pl0.y = l;
                bf16split(v10, h, l); ph1.x = h; pl1.x = l;
                bf16split(v11, h, l); ph1.y = h; pl1.y = l;
                *(__nv_bfloat162*)(chip + (size_t)r0 * sldc + cl)       = ph0;
                *(__nv_bfloat162*)(clop + (size_t)r0 * sldc + cl)       = pl0;
                *(__nv_bfloat162*)(chip + (size_t)(r0 + 8) * sldc + cl) = ph1;
                *(__nv_bfloat162*)(clop + (size_t)(r0 + 8) * sldc + cl) = pl1;
            } else {
                *(float2*)(outp + (size_t)r0 * oldc + cl)       = make_float2(v00, v01);
                *(float2*)(outp + (size_t)(r0 + 8) * oldc + cl) = make_float2(v10, v11);
            }
        }
    }
}

// ---------------- merged split + weight-fold kernel ----------------
#define N4_Z   1048576
#define N4_H0  1048576
#define N4_WO  8192
#define N4_WIH 24576
#define N4_WHH 12288
#define N4_TOT (N4_Z + N4_H0 + N4_WO + N4_WIH + N4_WHH)
#define N_WUV  131072
#define N_WCE  81920
#define N_WSTK 49152
#define N_ALL  (N4_TOT + N_WUV + N_WCE + N_WSTK + 384)

__device__ __forceinline__ void split4(const float4* src, bf16* hi, bf16* lo, int i) {
    float4 v = src[i];
    bf16 h, l;
    __nv_bfloat162 h0, l0, h1, l1;
    bf16split(v.x, h, l); h0.x = h; l0.x = l;
    bf16split(v.y, h, l); h0.y = h; l0.y = l;
    bf16split(v.z, h, l); h1.x = h; l1.x = l;
    bf16split(v.w, h, l); h1.y = h; l1.y = l;
    ((__nv_bfloat162*)hi)[i * 2]     = h0; ((__nv_bfloat162*)lo)[i * 2]     = l0;
    ((__nv_bfloat162*)hi)[i * 2 + 1] = h1; ((__nv_bfloat162*)lo)[i * 2 + 1] = l1;
}

__global__ void splitprep_all(const float* __restrict__ z, const float* __restrict__ h0,
                              const float* __restrict__ W_obj, const float* __restrict__ Wih,
                              const float* __restrict__ Whh,
                              const float* __restrict__ We, const float* __restrict__ Wc,
                              const float* __restrict__ Wl, const float* __restrict__ bl,
                              const float* __restrict__ Wsc, const float* __restrict__ bs,
                              const float* __restrict__ Wh, const float* __restrict__ bh) {
    int idx = blockIdx.x * blockDim.x + threadIdx.x;
    if (idx >= N_ALL) return;
    if (idx < N4_Z) { split4((const float4*)z, g_z_hi, g_z_lo, idx); return; }
    if ((idx -= N4_Z) < N4_H0) { split4((const float4*)h0, g_h0_hi, g_h0_lo, idx); return; }
    if ((idx -= N4_H0) < N4_WO) { split4((const float4*)W_obj, g_Wobj_hi, g_Wobj_lo, idx); return; }
    if ((idx -= N4_WO) < N4_WIH) { split4((const float4*)Wih, g_Wih_hi, g_Wih_lo, idx); return; }
    if ((idx -= N4_WIH) < N4_WHH) { split4((const float4*)Whh, g_Whh_hi, g_Whh_lo, idx); return; }
    idx -= N4_WHH;
    if (idx < N_WUV) {
        int n = idx >> 7, c = idx & 127;
        float v;
        if (n < 512) v = We[n * 512 + c] + We[n * 512 + 128 + c];
        else {
            int nn = n - 512;
            v = We[nn * 512 + 256 + c] + We[nn * 512 + 384 + c];
        }
        bf16 h, l; bf16split(v, h, l);
        g_WUV_hi[idx] = h; g_WUV_lo[idx] = l;
    } else if ((idx -= N_WUV) < N_WCE) {
        int n = idx / 640, c = idx % 640;
        float v = (c < 128) ? (Wc[n * 768 + c] + Wc[n * 768 + 128 + c])
                            : Wc[n * 768 + 128 + c];
        bf16 h, l; bf16split(v, h, l);
        g_WcE_hi[idx] = h; g_WcE_lo[idx] = l;
    } else if ((idx -= N_WCE) < N_WSTK) {
        int n = idx >> 7, c = idx & 127;
        const float* W = (n < 128) ? Wl : ((n < 256) ? Wsc : Wh);
        bf16 h, l; bf16split(W[(n & 127) * 128 + c], h, l);
        g_Wstk_hi[idx] = h; g_Wstk_lo[idx] = l;
    } else {
        idx -= N_WSTK;
        const float* bb = (idx < 128) ? bl : ((idx < 256) ? bs : bh);
        g_bstk[idx] = bb[idx & 127];
    }
}

// ---------------- GRU gate fusion (float4 vectorized, writes split h) ----------------
__device__ __forceinline__ float sigm(float x) { return 1.f / (1.f + __expf(-x)); }

__global__ void gru_gate(const float* __restrict__ gi, const float* __restrict__ gh,
                         const float* __restrict__ h0,
                         bf16* __restrict__ hhi, bf16* __restrict__ hlo) {
    int idx = blockIdx.x * blockDim.x + threadIdx.x;
    if (idx >= ROWS * 32) return;
    int m = idx >> 5, c4 = (idx & 31) * 4;
    const float* gim = gi + (size_t)m * 384;
    const float* ghm = gh + (size_t)m * 384;
    float4 gir = *(const float4*)(gim + c4);
    float4 giu = *(const float4*)(gim + 128 + c4);
    float4 gin = *(const float4*)(gim + 256 + c4);
    float4 ghr = *(const float4*)(ghm + c4);
    float4 ghu = *(const float4*)(ghm + 128 + c4);
    float4 ghn = *(const float4*)(ghm + 256 + c4);
    float4 h0v = *(const float4*)(h0 + (size_t)m * 128 + c4);
    float out[4];
    {
        float r = sigm(gir.x + ghr.x), u = sigm(giu.x + ghu.x);
        out[0] = (1.f - u) * tanhf(gin.x + r * ghn.x) + u * h0v.x;
        r = sigm(gir.y + ghr.y); u = sigm(giu.y + ghu.y);
        out[1] = (1.f - u) * tanhf(gin.y + r * ghn.y) + u * h0v.y;
        r = sigm(gir.z + ghr.z); u = sigm(giu.z + ghu.z);
        out[2] = (1.f - u) * tanhf(gin.z + r * ghn.z) + u * h0v.z;
        r = sigm(gir.w + ghr.w); u = sigm(giu.w + ghu.w);
        out[3] = (1.f - u) * tanhf(gin.w + r * ghn.w) + u * h0v.w;
    }
    __nv_bfloat162 ph0, pl0, ph1, pl1;
    bf16 h, l;
    bf16split(out[0], h, l); ph0.x = h; pl0.x = l;
    bf16split(out[1], h, l); ph0.y = h; pl0.y = l;
    bf16split(out[2], h, l); ph1.x = h; pl1.x = l;
    bf16split(out[3], h, l); ph1.y = h; pl1.y = l;
    __nv_bfloat162* ho = (__nv_bfloat162*)(hhi + (size_t)m * 128 + c4);
    __nv_bfloat162* lo2 = (__nv_bfloat162*)(hlo + (size_t)m * 128 + c4);
    ho[0] = ph0; ho[1] = ph1;
    lo2[0] = pl0; lo2[1] = pl1;
}

// ---------------- G4 combine: rel = p0 + p1 + bc -> split ----------------
__global__ void combine_rel(const float* __restrict__ bc) {
    int idx = blockIdx.x * blockDim.x + threadIdx.x;
    if (idx >= ROWS * 32) return;
    int m = idx >> 5, c4 = (idx & 31) * 4;
    float4 a = *(const float4*)(g_gi + (size_t)m * 128 + c4);
    float4 b = *(const float4*)(g_gh + (size_t)m * 128 + c4);
    float4 bcv = *(const float4*)(bc + c4);
    float v0 = a.x + b.x + bcv.x;
    float v1 = a.y + b.y + bcv.y;
    float v2 = a.z + b.z + bcv.z;
    float v3 = a.w + b.w + bcv.w;
    __nv_bfloat162 ph0, pl0, ph1, pl1;
    bf16 h, l;
    bf16split(v0, h, l); ph0.x = h; pl0.x = l;
    bf16split(v1, h, l); ph0.y = h; pl0.y = l;
    bf16split(v2, h, l); ph1.x = h; pl1.x = l;
    bf16split(v3, h, l); ph1.y = h; pl1.y = l;
    __nv_bfloat162* ho = (__nv_bfloat162*)(g_rel_hi + (size_t)m * 128 + c4);
    __nv_bfloat162* lo2 = (__nv_bfloat162*)(g_rel_lo + (size_t)m * 128 + c4);
    ho[0] = ph0; ho[1] = ph1;
    lo2[0] = pl0; lo2[1] = pl1;
}

// ---------------- pair stage: warp-per-object, atomic-free ----------------
__global__ void __launch_bounds__(512) pair_kernel(
    const float* __restrict__ UV, const float* __restrict__ Wa,
    const float* __restrict__ ba, const float* __restrict__ be,
    bf16* __restrict__ Ehi, bf16* __restrict__ Elo)
{
    extern __shared__ float smf[];
    float* Ub = smf;
    float* Vb = Ub + 16 * 512;

    const int b = blockIdx.x;
    const int tid = threadIdx.x;
    const int w = tid >> 5, lane = tid & 31;

    for (int i = tid; i < 16 * 512; i += 512) {
        int k = i >> 9, t = i & 511;
        const float* row = UV + (size_t)(b * 16 + k) * 1024;
        Ub[i] = row[t];
        Vb[i] = row[512 + t];
    }
    __syncthreads();

    const float ba0 = __ldg(&ba[0]);
    float uw[16], vw[16], ber[16], war[16], Ew[16];
#pragma unroll
    for (int c = 0; c < 16; c++) {
        int t = lane + 32 * c;
        uw[c] = Ub[w * 512 + t];
        vw[c] = Vb[w * 512 + t];
        ber[c] = __ldg(&be[t]);
        war[c] = __ldg(&Wa[t]);
        Ew[c] = 0.f;
    }

#pragma unroll 1
    for (int o = 0; o < K_OBJ; o++) {
        if (o == w) continue;
        const float* Urow = Ub + o * 512;
        const float* Vrow = Vb + o * 512;
        float e[16];
        float dot = 0.f;
        if (o > w) {
#pragma unroll
            for (int c = 0; c < 16; c++) {
                float x = uw[c] + Vrow[lane + 32 * c] + ber[c];
                x = (x > 0.f) ? x : (__expf(x) - 1.f);
                e[c] = x;
                dot += x * war[c];
            }
        } else {
#pragma unroll
            for (int c = 0; c < 16; c++) {
                float x = Urow[lane + 32 * c] + vw[c] + ber[c];
                x = (x > 0.f) ? x : (__expf(x) - 1.f);
                e[c] = x;
                dot += x * war[c];
            }
        }
#pragma unroll
        for (int off = 16; off > 0; off >>= 1) dot += __shfl_xor_sync(0xffffffffu, dot, off);
        float att = 1.f / (1.f + __expf(-(dot + ba0)));
#pragma unroll
        for (int c = 0; c < 16; c++) Ew[c] += att * e[c];
    }

    bf16* Eh = Ehi + ((size_t)b * 16 + w) * 512;
    bf16* El = Elo + ((size_t)b * 16 + w) * 512;
#pragma unroll
    for (int c = 0; c < 16; c++) {
        bf16 h, l; bf16split(Ew[c], h, l);
        Eh[lane + 32 * c] = h;
        El[lane + 32 * c] = l;
    }
}

// ---------------- host launcher ----------------
extern "C" void kernel_launch(void* const* d_in, const int* in_sizes, int n_in,
                              void* d_out, int out_size)
{
    const float* z    = (const float*)d_in[0];
    const float* h0   = (const float*)d_in[1];
    const float* W_obj= (const float*)d_in[2];
    const float* b_obj= (const float*)d_in[3];
    const float* Wih  = (const float*)d_in[4];
    const float* bih  = (const float*)d_in[5];
    const float* Whh  = (const float*)d_in[6];
    const float* bhh  = (const float*)d_in[7];
    const float* We   = (const float*)d_in[8];
    const float* be   = (const float*)d_in[9];
    const float* Wa   = (const float*)d_in[10];
    const float* ba   = (const float*)d_in[11];
    const float* Wc   = (const float*)d_in[12];
    const float* bc   = (const float*)d_in[13];
    const float* Wl   = (const float*)d_in[14];
    const float* bl   = (const float*)d_in[15];
    const float* Wsc  = (const float*)d_in[16];
    const float* bs   = (const float*)d_in[17];
    const float* Wh   = (const float*)d_in[18];
    const float* bh   = (const float*)d_in[19];

    float* out1 = (float*)d_out;
    float* out2 = out1 + (size_t)ROWS * 256;

    bf16 *p_z_hi, *p_z_lo, *p_ze_hi, *p_ze_lo;
    bf16 *p_h_hi, *p_h_lo, *p_E_hi, *p_E_lo, *p_rel_hi, *p_rel_lo;
    float *p_gi, *p_gh, *p_UV, *p_bstk;
    bf16 *p_Wobj_hi, *p_Wobj_lo, *p_Wih_hi, *p_Wih_lo;
    bf16 *p_WUV_hi, *p_WUV_lo, *p_WcE_hi, *p_WcE_lo, *p_Wstk_hi, *p_Wstk_lo;

    cudaGetSymbolAddress((void**)&p_z_hi,  g_z_hi);   cudaGetSymbolAddress((void**)&p_z_lo,  g_z_lo);
    cudaGetSymbolAddress((void**)&p_ze_hi, g_ze_hi);  cudaGetSymbolAddress((void**)&p_ze_lo, g_ze_lo);
    cudaGetSymbolAddress((void**)&p_h_hi,  g_h_hi);   cudaGetSymbolAddress((void**)&p_h_lo,  g_h_lo);
    cudaGetSymbolAddress((void**)&p_E_hi,  g_E_hi);   cudaGetSymbolAddress((void**)&p_E_lo,  g_E_lo);
    cudaGetSymbolAddress((void**)&p_rel_hi,g_rel_hi); cudaGetSymbolAddress((void**)&p_rel_lo,g_rel_lo);
    cudaGetSymbolAddress((void**)&p_gi, g_gi);
    cudaGetSymbolAddress((void**)&p_gh, g_gh);
    cudaGetSymbolAddress((void**)&p_UV, g_UV);
    cudaGetSymbolAddress((void**)&p_bstk, g_bstk);
    cudaGetSymbolAddress((void**)&p_Wobj_hi, g_Wobj_hi); cudaGetSymbolAddress((void**)&p_Wobj_lo, g_Wobj_lo);
    cudaGetSymbolAddress((void**)&p_Wih_hi,  g_Wih_hi);  cudaGetSymbolAddress((void**)&p_Wih_lo,  g_Wih_lo);
    cudaGetSymbolAddress((void**)&p_WUV_hi,  g_WUV_hi);  cudaGetSymbolAddress((void**)&p_WUV_lo,  g_WUV_lo);
    cudaGetSymbolAddress((void**)&p_WcE_hi,  g_WcE_hi);  cudaGetSymbolAddress((void**)&p_WcE_lo,  g_WcE_lo);
    cudaGetSymbolAddress((void**)&p_Wstk_hi, g_Wstk_hi); cudaGetSymbolAddress((void**)&p_Wstk_lo, g_Wstk_lo);

    const int SMEM_GEMM = 2 * STG_BYTES;   // 61440
    cudaFuncSetAttribute(gemm_mma<0,6>, cudaFuncAttributeMaxDynamicSharedMemorySize, SMEM_GEMM);
    cudaFuncSetAttribute(gemm_mma<0,0>, cudaFuncAttributeMaxDynamicSharedMemorySize, SMEM_GEMM);
    cudaFuncSetAttribute(gemm_mma<0,5>, cudaFuncAttributeMaxDynamicSharedMemorySize, SMEM_GEMM);
    cudaFuncSetAttribute(gemm_mma<0,2>, cudaFuncAttributeMaxDynamicSharedMemorySize, SMEM_GEMM);

    // merged splits + weight folds (one launch)
    splitprep_all<<<(N_ALL + 255) / 256, 256>>>(z, h0, W_obj, Wih, Whh,
                                                We, Wc, Wl, bl, Wsc, bs, Wh, bh);

    const int MB = ROWS / 128;   // 256

    // G1 (x<4: z_embed = elu(z@Wobj^T+b_obj) -> ze split) + G2b (x>=4: gh = h0@Whh^T+bhh)
    gemm_mma<0,6><<<dim3(10, MB), 256, SMEM_GEMM>>>(
        p_z_hi, p_z_lo, 128, 128, nullptr, nullptr, 0,
        p_Wobj_hi, p_Wobj_lo, b_obj, nullptr, p_ze_hi, p_ze_lo, 256, (float*)bhh, 128);

    // G2a: gi = z_embed @ Wih^T + bih  [ROWS, 384] f32
    gemm_mma<0,0><<<dim3(6, MB), 256, SMEM_GEMM>>>(
        p_ze_hi, p_ze_lo, 256, 256, nullptr, nullptr, 0,
        p_Wih_hi, p_Wih_lo, bih, p_gi, nullptr, nullptr, 384, nullptr, 256);

    // GRU gates -> h (split)
    gru_gate<<<(ROWS * 32 + 255) / 256, 256>>>(p_gi, p_gh, h0, p_h_hi, p_h_lo);

    // G3: UV = h @ W_UV^T  [ROWS, 1024] f32
    gemm_mma<0,0><<<dim3(16, MB), 256, SMEM_GEMM>>>(
        p_h_hi, p_h_lo, 128, 128, nullptr, nullptr, 0,
        p_WUV_hi, p_WUV_lo, nullptr, p_UV, nullptr, nullptr, 1024, nullptr, 128);

    // pair stage -> E (split) [ROWS, 512], atomic-free
    size_t psmem = (2 * 16 * 512) * sizeof(float);
    cudaFuncSetAttribute(pair_kernel, cudaFuncAttributeMaxDynamicSharedMemorySize, (int)psmem);
    pair_kernel<<<B_SZ, 512, psmem>>>(p_UV, Wa, ba, be, p_E_hi, p_E_lo);

    // G4: split-K x2 in one launch (Kd=320 per half); partials -> g_gi / g_gh
    gemm_mma<0,5><<<dim3(4, MB), 256, SMEM_GEMM>>>(
        p_h_hi, p_h_lo, 128, 128, p_E_hi, p_E_lo, 512,
        p_WcE_hi, p_WcE_lo, nullptr, nullptr, nullptr, nullptr, 0, nullptr, 320);
    // rel = p0 + p1 + bc -> split
    combine_rel<<<(ROWS * 32 + 255) / 256, 256>>>(bc);

    // G5: [loc|scale|h_out] = rel @ Wstk^T + bstk, final f32 split outputs
    gemm_mma<0,2><<<dim3(6, MB), 256, SMEM_GEMM>>>(
        p_rel_hi, p_rel_lo, 128, 128, nullptr, nullptr, 0,
        p_Wstk_hi, p_Wstk_lo, p_bstk, out1, nullptr, nullptr, 0, out2, 128);
}

// round 15
// speedup vs baseline: 1.0485x; 1.0079x over previous
#include <cuda_runtime.h>
#include <cuda_bf16.h>
#include <math.h>
#include <stdint.h>

#define B_SZ   2048
#define K_OBJ  16
#define ROWS   (B_SZ * K_OBJ)      // 32768
#define NPAIR  120

typedef __nv_bfloat16 bf16;

// ---------------- scratch (device globals; no allocation allowed) ----------------
__device__ __align__(16) bf16 g_z_hi  [(size_t)ROWS * 128];
__device__ __align__(16) bf16 g_z_lo  [(size_t)ROWS * 128];
__device__ __align__(16) bf16 g_h0_hi [(size_t)ROWS * 128];
__device__ __align__(16) bf16 g_h0_lo [(size_t)ROWS * 128];
__device__ __align__(16) bf16 g_ze_hi [(size_t)ROWS * 256];
__device__ __align__(16) bf16 g_ze_lo [(size_t)ROWS * 256];
__device__ __align__(16) bf16 g_h_hi  [(size_t)ROWS * 128];
__device__ __align__(16) bf16 g_h_lo  [(size_t)ROWS * 128];
__device__ __align__(16) bf16 g_E_hi  [(size_t)ROWS * 512];
__device__ __align__(16) bf16 g_E_lo  [(size_t)ROWS * 512];
__device__ __align__(16) bf16 g_rel_hi[(size_t)ROWS * 128];
__device__ __align__(16) bf16 g_rel_lo[(size_t)ROWS * 128];
__device__ __align__(16) float g_gi [(size_t)ROWS * 384];   // also G4 partial0 (ld128)
__device__ __align__(16) float g_gh [(size_t)ROWS * 384];   // also G4 partial1 (ld128)
__device__ __align__(16) float g_UV [(size_t)ROWS * 1024];
__device__ __align__(16) bf16 g_Wobj_hi[256 * 128],  g_Wobj_lo[256 * 128];
__device__ __align__(16) bf16 g_Wih_hi [384 * 256],  g_Wih_lo [384 * 256];
__device__ __align__(16) bf16 g_Whh_hi [384 * 128],  g_Whh_lo [384 * 128];
__device__ __align__(16) bf16 g_WUV_hi [1024 * 128], g_WUV_lo [1024 * 128];
__device__ __align__(16) bf16 g_WcE_hi [128 * 640],  g_WcE_lo [128 * 640];
__device__ __align__(16) bf16 g_Wstk_hi[384 * 128],  g_Wstk_lo[384 * 128];
__device__ __align__(16) float g_bstk[384];
__device__ __align__(16) float g_buv[1024];     // [be/2 | be/2] folded into G3 bias

// ---------------- helpers ----------------
__device__ __forceinline__ void bf16split(float x, bf16& h, bf16& l) {
    h = __float2bfloat16_rn(x);
    l = __float2bfloat16_rn(x - __bfloat162float(h));
}

__device__ __forceinline__ uint32_t smem_u32(const void* p) {
    uint32_t a;
    asm("{ .reg .u64 t; cvta.to.shared.u64 t, %1; cvt.u32.u64 %0, t; }" : "=r"(a) : "l"(p));
    return a;
}

__device__ __forceinline__ void cp16(uint32_t dst, const void* src) {
    asm volatile("cp.async.ca.shared.global [%0], [%1], 16;" :: "r"(dst), "l"(src) : "memory");
}
#define CP_COMMIT() asm volatile("cp.async.commit_group;" ::: "memory")
#define CP_WAIT(n)  asm volatile("cp.async.wait_group %0;" :: "n"(n) : "memory")

__device__ __forceinline__ void mma16(float* d, const uint32_t* a, const uint32_t* b) {
    asm volatile(
        "mma.sync.aligned.m16n8k16.row.col.f32.bf16.bf16.f32 "
        "{%0,%1,%2,%3}, {%4,%5,%6,%7}, {%8,%9}, {%0,%1,%2,%3};"
        : "+f"(d[0]), "+f"(d[1]), "+f"(d[2]), "+f"(d[3])
        : "r"(a[0]), "r"(a[1]), "r"(a[2]), "r"(a[3]), "r"(b[0]), "r"(b[1]));
}

// ---------------- tensor-core bf16x3 NT GEMM, CTA 128x64, 3 CTAs/SM (R12) ----------------
// OUTM: 0 f32 C; 2 final f32 split (C ld256 / C2 ld128);
//       5 G4 split-K (grid.x packs 2 K-halves; raw f32 partials to g_gi/g_gh ld128);
//       6 merged G1(x<4: elu+split->Chi/Clo ld256) / G2b(x>=4: f32->g_gh ld384, bias=C2).
#define PADW 20
#define A_TW  2560   // 128 * PADW
#define B_TW  1280   //  64 * PADW
#define STG_WORDS 7680
#define STG_BYTES (STG_WORDS * 4)

template <int ACT, int OUTM>
__global__ void __launch_bounds__(256, 3) gemm_mma(
    const bf16* __restrict__ X1hi, const bf16* __restrict__ X1lo, int ld1, int k1,
    const bf16* __restrict__ X2hi, const bf16* __restrict__ X2lo, int ld2,
    const bf16* __restrict__ Whi, const bf16* __restrict__ Wlo,
    const float* __restrict__ bias,
    float* __restrict__ C, bf16* __restrict__ Chi, bf16* __restrict__ Clo,
    int ldc, float* __restrict__ C2, int Kd)
{
    extern __shared__ uint32_t smw[];
    const uint32_t sb = smem_u32(smw);

    const int tid = threadIdx.x;
    const int lane = tid & 31;
    const int wid = tid >> 5;
    const int warp_m = wid >> 1;
    const int warp_n = wid & 1;
    const int gid = lane >> 2;
    const int tig = lane & 3;
    const int bm = blockIdx.y * 128;

    int bx = blockIdx.x;
    const bf16 *x1hi = X1hi, *x1lo = X1lo, *x2hi = X2hi, *x2lo = X2lo;
    const bf16 *whi = Whi, *wlo = Wlo;
    const float* biasp = bias;
    int l1 = ld1, l2 = ld2, kb1 = k1, wld = Kd, woff = 0;
    int subq = 0;
    if (OUTM == 5) {
        subq = bx >> 1; bx &= 1;
        wld = 640; biasp = nullptr;
        if (subq == 1) {
            x1hi = g_E_hi + 192; x1lo = g_E_lo + 192; l1 = 512; kb1 = 1 << 30;
            woff = 320;
        }
    }
    if (OUTM == 6) {
        if (bx >= 4) {
            subq = 1; bx -= 4;
            x1hi = g_h0_hi; x1lo = g_h0_lo; l1 = 128; kb1 = 128;
            whi = g_Whh_hi; wlo = g_Whh_lo;
            biasp = (const float*)C2;
        }
    }
    const int bn = bx * 64;

    float acc[2][4][4];
#pragma unroll
    for (int mi = 0; mi < 2; mi++)
#pragma unroll
        for (int nf = 0; nf < 4; nf++)
#pragma unroll
            for (int e = 0; e < 4; e++) acc[mi][nf][e] = 0.f;

    auto load_slab = [&](int k0, int s) {
        const bf16 *ahi, *alo; int xld, xc;
        if (k0 < kb1) { ahi = x1hi; alo = x1lo; xld = l1; xc = k0; }
        else          { ahi = x2hi; alo = x2lo; xld = l2; xc = k0 - kb1; }
        const uint32_t st = sb + s * STG_BYTES;
#pragma unroll
        for (int j = 0; j < 2; j++) {
            int c = tid + j * 256;
            int row = c >> 2, ch = c & 3;
            uint32_t so = (uint32_t)(row * PADW + ch * 4) * 4;
            const size_t ga = (size_t)(bm + row) * xld + xc + ch * 8;
            cp16(st + so,            ahi + ga);
            cp16(st + A_TW * 4 + so, alo + ga);
        }
        {
            int row = tid >> 2, ch = tid & 3;
            uint32_t so = (uint32_t)(row * PADW + ch * 4) * 4;
            const size_t gw = (size_t)(bn + row) * wld + woff + k0 + ch * 8;
            cp16(st + 2 * A_TW * 4 + so,          whi + gw);
            cp16(st + (2 * A_TW + B_TW) * 4 + so, wlo + gw);
        }
    };

    load_slab(0, 0);
    CP_COMMIT();

    const int nIter = Kd >> 5;
#pragma unroll 1
    for (int i = 0; i < nIter; i++) {
        CP_WAIT(0);
        __syncthreads();
        if (i + 1 < nIter) {
            load_slab((i + 1) * 32, (i + 1) & 1);
            CP_COMMIT();
        }

        const uint32_t* sA  = smw + (i & 1) * STG_WORDS;
        const uint32_t* sAl = sA + A_TW;
        const uint32_t* sB  = sA + 2 * A_TW;
        const uint32_t* sBl = sA + 2 * A_TW + B_TW;

#pragma unroll
        for (int h = 0; h < 2; h++) {
            const int kb = h * 8 + tig;
            uint32_t ah[2][4], al[2][4];
#pragma unroll
            for (int mi = 0; mi < 2; mi++) {
                int am = (warp_m * 32 + mi * 16 + gid) * PADW;
                ah[mi][0] = sA [am + kb];
                ah[mi][1] = sA [am + 8 * PADW + kb];
                ah[mi][2] = sA [am + kb + 4];
                ah[mi][3] = sA [am + 8 * PADW + kb + 4];
                al[mi][0] = sAl[am + kb];
                al[mi][1] = sAl[am + 8 * PADW + kb];
                al[mi][2] = sAl[am + kb + 4];
                al[mi][3] = sAl[am + 8 * PADW + kb + 4];
            }
            uint32_t bf[4][2];
#pragma unroll
            for (int nf = 0; nf < 4; nf++) {
                int an = (warp_n * 32 + nf * 8 + gid) * PADW;
                bf[nf][0] = sB[an + kb];
                bf[nf][1] = sB[an + kb + 4];
            }
#pragma unroll
            for (int mi = 0; mi < 2; mi++)
#pragma unroll
                for (int nf = 0; nf < 4; nf++)
                    mma16(acc[mi][nf], ah[mi], bf[nf]);
#pragma unroll
            for (int mi = 0; mi < 2; mi++)
#pragma unroll
                for (int nf = 0; nf < 4; nf++)
                    mma16(acc[mi][nf], al[mi], bf[nf]);
#pragma unroll
            for (int nf = 0; nf < 4; nf++) {
                int an = (warp_n * 32 + nf * 8 + gid) * PADW;
                bf[nf][0] = sBl[an + kb];
                bf[nf][1] = sBl[an + kb + 4];
            }
#pragma unroll
            for (int mi = 0; mi < 2; mi++)
#pragma unroll
                for (int nf = 0; nf < 4; nf++)
                    mma16(acc[mi][nf], ah[mi], bf[nf]);
        }
    }

    // ---- epilogue ----
    float* outp = C; int oldc = ldc, ncol0 = bn;
    bf16 *chip = Chi, *clop = Clo; int sldc = ldc;
    bool splitOut = (OUTM == 1);
    bool doElu = (ACT == 1);
    if (OUTM == 2) {
        if (bn >= 256) { outp = C2; oldc = 128; ncol0 = bn - 256; }
        else           { outp = C;  oldc = 256; ncol0 = bn; }
    }
    if (OUTM == 5) { outp = subq ? g_gh : g_gi; oldc = 128; ncol0 = bn; }
    if (OUTM == 6) {
        if (subq == 0) { splitOut = true; doElu = true; sldc = 256; }
        else           { outp = g_gh; oldc = 384; ncol0 = bn; }
    }

#pragma unroll
    for (int mi = 0; mi < 2; mi++) {
        int r0 = bm + warp_m * 32 + mi * 16 + gid;
#pragma unroll
        for (int nf = 0; nf < 4; nf++) {
            int cg = bn + warp_n * 32 + nf * 8 + tig * 2;
            int cl = ncol0 + warp_n * 32 + nf * 8 + tig * 2;
            float b0 = 0.f, b1 = 0.f;
            if (biasp) { float2 bv = *(const float2*)(biasp + cg); b0 = bv.x; b1 = bv.y; }
            float v00 = acc[mi][nf][0] + b0;
            float v01 = acc[mi][nf][1] + b1;
            float v10 = acc[mi][nf][2] + b0;
            float v11 = acc[mi][nf][3] + b1;
            if (doElu) {
                v00 = (v00 > 0.f) ? v00 : (__expf(v00) - 1.f);
                v01 = (v01 > 0.f) ? v01 : (__expf(v01) - 1.f);
                v10 = (v10 > 0.f) ? v10 : (__expf(v10) - 1.f);
                v11 = (v11 > 0.f) ? v11 : (__expf(v11) - 1.f);
            }
            if (splitOut) {
                bf16 h, l;
                __nv_bfloat162 ph0, pl0, ph1, pl1;
                bf16split(v00, h, l); ph0.x = h; pl0.x = l;
                bf16split(v01, h, l); ph0.y = h; pl0.y = l;
                bf16split(v10, h, l); ph1.x = h; pl1.x = l;
                bf16split(v11, h, l); ph1.y = h; pl1.y = l;
                *(__nv_bfloat162*)(chip + (size_t)r0 * sldc + cl)       = ph0;
                *(__nv_bfloat162*)(clop + (size_t)r0 * sldc + cl)       = pl0;
                *(__nv_bfloat162*)(chip + (size_t)(r0 + 8) * sldc + cl) = ph1;
                *(__nv_bfloat162*)(clop + (size_t)(r0 + 8) * sldc + cl) = pl1;
            } else {
                *(float2*)(outp + (size_t)r0 * oldc + cl)       = make_float2(v00, v01);
                *(float2*)(outp + (size_t)(r0 + 8) * oldc + cl) = make_float2(v10, v11);
            }
        }
    }
}

// ---------------- merged split + weight-fold kernel ----------------
#define N4_Z   1048576
#define N4_H0  1048576
#define N4_WO  8192
#define N4_WIH 24576
#define N4_WHH 12288
#define N4_TOT (N4_Z + N4_H0 + N4_WO + N4_WIH + N4_WHH)
#define N_WUV  131072
#define N_WCE  81920
#define N_WSTK 49152
#define N_ALL  (N4_TOT + N_WUV + N_WCE + N_WSTK + 384 + 1024)

__device__ __forceinline__ void split4(const float4* src, bf16* hi, bf16* lo, int i) {
    float4 v = src[i];
    bf16 h, l;
    __nv_bfloat162 h0, l0, h1, l1;
    bf16split(v.x, h, l); h0.x = h; l0.x = l;
    bf16split(v.y, h, l); h0.y = h; l0.y = l;
    bf16split(v.z, h, l); h1.x = h; l1.x = l;
    bf16split(v.w, h, l); h1.y = h; l1.y = l;
    ((__nv_bfloat162*)hi)[i * 2]     = h0; ((__nv_bfloat162*)lo)[i * 2]     = l0;
    ((__nv_bfloat162*)hi)[i * 2 + 1] = h1; ((__nv_bfloat162*)lo)[i * 2 + 1] = l1;
}

__global__ void splitprep_all(const float* __restrict__ z, const float* __restrict__ h0,
                              const float* __restrict__ W_obj, const float* __restrict__ Wih,
                              const float* __restrict__ Whh,
                              const float* __restrict__ We, const float* __restrict__ Wc,
                              const float* __restrict__ Wl, const float* __restrict__ bl,
                              const float* __restrict__ Wsc, const float* __restrict__ bs,
                              const float* __restrict__ Wh, const float* __restrict__ bh,
                              const float* __restrict__ be) {
    int idx = blockIdx.x * blockDim.x + threadIdx.x;
    if (idx >= N_ALL) return;
    if (idx < N4_Z) { split4((const float4*)z, g_z_hi, g_z_lo, idx); return; }
    if ((idx -= N4_Z) < N4_H0) { split4((const float4*)h0, g_h0_hi, g_h0_lo, idx); return; }
    if ((idx -= N4_H0) < N4_WO) { split4((const float4*)W_obj, g_Wobj_hi, g_Wobj_lo, idx); return; }
    if ((idx -= N4_WO) < N4_WIH) { split4((const float4*)Wih, g_Wih_hi, g_Wih_lo, idx); return; }
    if ((idx -= N4_WIH) < N4_WHH) { split4((const float4*)Whh, g_Whh_hi, g_Whh_lo, idx); return; }
    idx -= N4_WHH;
    if (idx < N_WUV) {
        int n = idx >> 7, c = idx & 127;
        float v;
        if (n < 512) v = We[n * 512 + c] + We[n * 512 + 128 + c];
        else {
            int nn = n - 512;
            v = We[nn * 512 + 256 + c] + We[nn * 512 + 384 + c];
        }
        bf16 h, l; bf16split(v, h, l);
        g_WUV_hi[idx] = h; g_WUV_lo[idx] = l;
    } else if ((idx -= N_WUV) < N_WCE) {
        int n = idx / 640, c = idx % 640;
        float v = (c < 128) ? (Wc[n * 768 + c] + Wc[n * 768 + 128 + c])
                            : Wc[n * 768 + 128 + c];
        bf16 h, l; bf16split(v, h, l);
        g_WcE_hi[idx] = h; g_WcE_lo[idx] = l;
    } else if ((idx -= N_WCE) < N_WSTK) {
        int n = idx >> 7, c = idx & 127;
        const float* W = (n < 128) ? Wl : ((n < 256) ? Wsc : Wh);
        bf16 h, l; bf16split(W[(n & 127) * 128 + c], h, l);
        g_Wstk_hi[idx] = h; g_Wstk_lo[idx] = l;
    } else if ((idx -= N_WSTK) < 384) {
        const float* bb = (idx < 128) ? bl : ((idx < 256) ? bs : bh);
        g_bstk[idx] = bb[idx & 127];
    } else {
        idx -= 384;                       // 0..1023
        g_buv[idx] = 0.5f * be[idx & 511];
    }
}

// ---------------- GRU gate fusion (float4 vectorized, writes split h) ----------------
__device__ __forceinline__ float sigm(float x) { return 1.f / (1.f + __expf(-x)); }

__global__ void gru_gate(const float* __restrict__ gi, const float* __restrict__ gh,
                         const float* __restrict__ h0,
                         bf16* __restrict__ hhi, bf16* __restrict__ hlo) {
    int idx = blockIdx.x * blockDim.x + threadIdx.x;
    if (idx >= ROWS * 32) return;
    int m = idx >> 5, c4 = (idx & 31) * 4;
    const float* gim = gi + (size_t)m * 384;
    const float* ghm = gh + (size_t)m * 384;
    float4 gir = *(const float4*)(gim + c4);
    float4 giu = *(const float4*)(gim + 128 + c4);
    float4 gin = *(const float4*)(gim + 256 + c4);
    float4 ghr = *(const float4*)(ghm + c4);
    float4 ghu = *(const float4*)(ghm + 128 + c4);
    float4 ghn = *(const float4*)(ghm + 256 + c4);
    float4 h0v = *(const float4*)(h0 + (size_t)m * 128 + c4);
    float out[4];
    {
        float r = sigm(gir.x + ghr.x), u = sigm(giu.x + ghu.x);
        out[0] = (1.f - u) * tanhf(gin.x + r * ghn.x) + u * h0v.x;
        r = sigm(gir.y + ghr.y); u = sigm(giu.y + ghu.y);
        out[1] = (1.f - u) * tanhf(gin.y + r * ghn.y) + u * h0v.y;
        r = sigm(gir.z + ghr.z); u = sigm(giu.z + ghu.z);
        out[2] = (1.f - u) * tanhf(gin.z + r * ghn.z) + u * h0v.z;
        r = sigm(gir.w + ghr.w); u = sigm(giu.w + ghu.w);
        out[3] = (1.f - u) * tanhf(gin.w + r * ghn.w) + u * h0v.w;
    }
    __nv_bfloat162 ph0, pl0, ph1, pl1;
    bf16 h, l;
    bf16split(out[0], h, l); ph0.x = h; pl0.x = l;
    bf16split(out[1], h, l); ph0.y = h; pl0.y = l;
    bf16split(out[2], h, l); ph1.x = h; pl1.x = l;
    bf16split(out[3], h, l); ph1.y = h; pl1.y = l;
    __nv_bfloat162* ho = (__nv_bfloat162*)(hhi + (size_t)m * 128 + c4);
    __nv_bfloat162* lo2 = (__nv_bfloat162*)(hlo + (size_t)m * 128 + c4);
    ho[0] = ph0; ho[1] = ph1;
    lo2[0] = pl0; lo2[1] = pl1;
}

// ---------------- G4 combine: rel = p0 + p1 + bc -> split ----------------
__global__ void combine_rel(const float* __restrict__ bc) {
    int idx = blockIdx.x * blockDim.x + threadIdx.x;
    if (idx >= ROWS * 32) return;
    int m = idx >> 5, c4 = (idx & 31) * 4;
    float4 a = *(const float4*)(g_gi + (size_t)m * 128 + c4);
    float4 b = *(const float4*)(g_gh + (size_t)m * 128 + c4);
    float4 bcv = *(const float4*)(bc + c4);
    float v0 = a.x + b.x + bcv.x;
    float v1 = a.y + b.y + bcv.y;
    float v2 = a.z + b.z + bcv.z;
    float v3 = a.w + b.w + bcv.w;
    __nv_bfloat162 ph0, pl0, ph1, pl1;
    bf16 h, l;
    bf16split(v0, h, l); ph0.x = h; pl0.x = l;
    bf16split(v1, h, l); ph0.y = h; pl0.y = l;
    bf16split(v2, h, l); ph1.x = h; pl1.x = l;
    bf16split(v3, h, l); ph1.y = h; pl1.y = l;
    __nv_bfloat162* ho = (__nv_bfloat162*)(g_rel_hi + (size_t)m * 128 + c4);
    __nv_bfloat162* lo2 = (__nv_bfloat162*)(g_rel_lo + (size_t)m * 128 + c4);
    ho[0] = ph0; ho[1] = ph1;
    lo2[0] = pl0; lo2[1] = pl1;
}

// ---------------- pair stage: 2 warps per object, 1024 threads, atomic-free ----------------
// be pre-folded into UV (G3 bias = [be/2 | be/2]). Warp (half*16 + objw) handles
// channels [half*256, half*256+256) of object objw. Cross-warp dot partials exchanged
// via double-buffered smem (write -> syncthreads -> read; alternating buffers).
__global__ void __launch_bounds__(1024, 1) pair_kernel(
    const float* __restrict__ UV, const float* __restrict__ Wa,
    const float* __restrict__ ba,
    bf16* __restrict__ Ehi, bf16* __restrict__ Elo)
{
    extern __shared__ float smf[];
    float* Ub   = smf;                  // 16*512
    float* Vb   = Ub + 16 * 512;        // 16*512
    float* dotp = Vb + 16 * 512;        // 2*32

    const int b = blockIdx.x;
    const int tid = threadIdx.x;
    const int wid = tid >> 5, lane = tid & 31;
    const int objw = wid & 15;
    const int half = wid >> 4;          // 0 or 1
    const int cbase = half * 256 + lane;

    // fill: 16 rows x 1024 floats, float4 loads
    for (int i = tid; i < 4096; i += 1024) {
        int k = i >> 8, t4 = i & 255;
        float4 v = *(const float4*)(UV + ((size_t)(b * 16 + k)) * 1024 + t4 * 4);
        float* dst = (t4 < 128) ? (Ub + k * 512 + t4 * 4)
                                : (Vb + k * 512 + (t4 - 128) * 4);
        *(float4*)dst = v;
    }
    __syncthreads();

    const float ba0 = __ldg(&ba[0]);
    float uw[8], vw[8], war[8], Ew[8];
#pragma unroll
    for (int c = 0; c < 8; c++) {
        int t = cbase + 32 * c;
        uw[c] = Ub[objw * 512 + t];
        vw[c] = Vb[objw * 512 + t];
        war[c] = __ldg(&Wa[t]);
        Ew[c] = 0.f;
    }

#pragma unroll 1
    for (int o = 0; o < K_OBJ; o++) {
        const bool active = (o != objw);
        float e[8];
        float dot = 0.f;
        if (active) {
            if (o > objw) {
                const float* Vrow = Vb + o * 512;
#pragma unroll
                for (int c = 0; c < 8; c++) {
                    float x = uw[c] + Vrow[cbase + 32 * c];
                    x = (x > 0.f) ? x : (__expf(x) - 1.f);
                    e[c] = x;
                    dot += x * war[c];
                }
            } else {
                const float* Urow = Ub + o * 512;
#pragma unroll
                for (int c = 0; c < 8; c++) {
                    float x = Urow[cbase + 32 * c] + vw[c];
                    x = (x > 0.f) ? x : (__expf(x) - 1.f);
                    e[c] = x;
                    dot += x * war[c];
                }
            }
#pragma unroll
            for (int off = 16; off > 0; off >>= 1) dot += __shfl_xor_sync(0xffffffffu, dot, off);
        }
        if (lane == 0) dotp[(o & 1) * 32 + wid] = dot;
        __syncthreads();
        if (active) {
            float dsum = dot + dotp[(o & 1) * 32 + (wid ^ 16)];
            float att = 1.f / (1.f + __expf(-(dsum + ba0)));
#pragma unroll
            for (int c = 0; c < 8; c++) Ew[c] += att * e[c];
        }
    }

    bf16* Eh = Ehi + ((size_t)b * 16 + objw) * 512;
    bf16* El = Elo + ((size_t)b * 16 + objw) * 512;
#pragma unroll
    for (int c = 0; c < 8; c++) {
        bf16 h, l; bf16split(Ew[c], h, l);
        Eh[cbase + 32 * c] = h;
        El[cbase + 32 * c] = l;
    }
}

// ---------------- host launcher ----------------
extern "C" void kernel_launch(void* const* d_in, const int* in_sizes, int n_in,
                              void* d_out, int out_size)
{
    const float* z    = (const float*)d_in[0];
    const float* h0   = (const float*)d_in[1];
    const float* W_obj= (const float*)d_in[2];
    const float* b_obj= (const float*)d_in[3];
    const float* Wih  = (const float*)d_in[4];
    const float* bih  = (const float*)d_in[5];
    const float* Whh  = (const float*)d_in[6];
    const float* bhh  = (const float*)d_in[7];
    const float* We   = (const float*)d_in[8];
    const float* be   = (const float*)d_in[9];
    const float* Wa   = (const float*)d_in[10];
    const float* ba   = (const float*)d_in[11];
    const float* Wc   = (const float*)d_in[12];
    const float* bc   = (const float*)d_in[13];
    const float* Wl   = (const float*)d_in[14];
    const float* bl   = (const float*)d_in[15];
    const float* Wsc  = (const float*)d_in[16];
    const float* bs   = (const float*)d_in[17];
    const float* Wh   = (const float*)d_in[18];
    const float* bh   = (const float*)d_in[19];

    float* out1 = (float*)d_out;
    float* out2 = out1 + (size_t)ROWS * 256;

    bf16 *p_z_hi, *p_z_lo, *p_ze_hi, *p_ze_lo;
    bf16 *p_h_hi, *p_h_lo, *p_E_hi, *p_E_lo, *p_rel_hi, *p_rel_lo;
    float *p_gi, *p_gh, *p_UV, *p_bstk, *p_buv;
    bf16 *p_Wobj_hi, *p_Wobj_lo, *p_Wih_hi, *p_Wih_lo;
    bf16 *p_WUV_hi, *p_WUV_lo, *p_WcE_hi, *p_WcE_lo, *p_Wstk_hi, *p_Wstk_lo;

    cudaGetSymbolAddress((void**)&p_z_hi,  g_z_hi);   cudaGetSymbolAddress((void**)&p_z_lo,  g_z_lo);
    cudaGetSymbolAddress((void**)&p_ze_hi, g_ze_hi);  cudaGetSymbolAddress((void**)&p_ze_lo, g_ze_lo);
    cudaGetSymbolAddress((void**)&p_h_hi,  g_h_hi);   cudaGetSymbolAddress((void**)&p_h_lo,  g_h_lo);
    cudaGetSymbolAddress((void**)&p_E_hi,  g_E_hi);   cudaGetSymbolAddress((void**)&p_E_lo,  g_E_lo);
    cudaGetSymbolAddress((void**)&p_rel_hi,g_rel_hi); cudaGetSymbolAddress((void**)&p_rel_lo,g_rel_lo);
    cudaGetSymbolAddress((void**)&p_gi, g_gi);
    cudaGetSymbolAddress((void**)&p_gh, g_gh);
    cudaGetSymbolAddress((void**)&p_UV, g_UV);
    cudaGetSymbolAddress((void**)&p_bstk, g_bstk);
    cudaGetSymbolAddress((void**)&p_buv, g_buv);
    cudaGetSymbolAddress((void**)&p_Wobj_hi, g_Wobj_hi); cudaGetSymbolAddress((void**)&p_Wobj_lo, g_Wobj_lo);
    cudaGetSymbolAddress((void**)&p_Wih_hi,  g_Wih_hi);  cudaGetSymbolAddress((void**)&p_Wih_lo,  g_Wih_lo);
    cudaGetSymbolAddress((void**)&p_WUV_hi,  g_WUV_hi);  cudaGetSymbolAddress((void**)&p_WUV_lo,  g_WUV_lo);
    cudaGetSymbolAddress((void**)&p_WcE_hi,  g_WcE_hi);  cudaGetSymbolAddress((void**)&p_WcE_lo,  g_WcE_lo);
    cudaGetSymbolAddress((void**)&p_Wstk_hi, g_Wstk_hi); cudaGetSymbolAddress((void**)&p_Wstk_lo, g_Wstk_lo);

    const int SMEM_GEMM = 2 * STG_BYTES;   // 61440
    cudaFuncSetAttribute(gemm_mma<0,6>, cudaFuncAttributeMaxDynamicSharedMemorySize, SMEM_GEMM);
    cudaFuncSetAttribute(gemm_mma<0,0>, cudaFuncAttributeMaxDynamicSharedMemorySize, SMEM_GEMM);
    cudaFuncSetAttribute(gemm_mma<0,5>, cudaFuncAttributeMaxDynamicSharedMemorySize, SMEM_GEMM);
    cudaFuncSetAttribute(gemm_mma<0,2>, cudaFuncAttributeMaxDynamicSharedMemorySize, SMEM_GEMM);

    // merged splits + weight folds (one launch)
    splitprep_all<<<(N_ALL + 255) / 256, 256>>>(z, h0, W_obj, Wih, Whh,
                                                We, Wc, Wl, bl, Wsc, bs, Wh, bh, be);

    const int MB = ROWS / 128;   // 256

    // G1 (x<4: z_embed = elu(z@Wobj^T+b_obj) -> ze split) + G2b (x>=4: gh = h0@Whh^T+bhh)
    gemm_mma<0,6><<<dim3(10, MB), 256, SMEM_GEMM>>>(
        p_z_hi, p_z_lo, 128, 128, nullptr, nullptr, 0,
        p_Wobj_hi, p_Wobj_lo, b_obj, nullptr, p_ze_hi, p_ze_lo, 256, (float*)bhh, 128);

    // G2a: gi = z_embed @ Wih^T + bih  [ROWS, 384] f32
    gemm_mma<0,0><<<dim3(6, MB), 256, SMEM_GEMM>>>(
        p_ze_hi, p_ze_lo, 256, 256, nullptr, nullptr, 0,
        p_Wih_hi, p_Wih_lo, bih, p_gi, nullptr, nullptr, 384, nullptr, 256);

    // GRU gates -> h (split)
    gru_gate<<<(ROWS * 32 + 255) / 256, 256>>>(p_gi, p_gh, h0, p_h_hi, p_h_lo);

    // G3: UV = h @ W_UV^T + [be/2 | be/2]  [ROWS, 1024] f32
    gemm_mma<0,0><<<dim3(16, MB), 256, SMEM_GEMM>>>(
        p_h_hi, p_h_lo, 128, 128, nullptr, nullptr, 0,
        p_WUV_hi, p_WUV_lo, p_buv, p_UV, nullptr, nullptr, 1024, nullptr, 128);

    // pair stage -> E (split) [ROWS, 512]; 1024 threads, 2 warps/object
    size_t psmem = (2 * 16 * 512 + 64) * sizeof(float);   // 65792
    cudaFuncSetAttribute(pair_kernel, cudaFuncAttributeMaxDynamicSharedMemorySize, (int)psmem);
    pair_kernel<<<B_SZ, 1024, psmem>>>(p_UV, Wa, ba, p_E_hi, p_E_lo);

    // G4: split-K x2 in one launch (Kd=320 per half); partials -> g_gi / g_gh
    gemm_mma<0,5><<<dim3(4, MB), 256, SMEM_GEMM>>>(
        p_h_hi, p_h_lo, 128, 128, p_E_hi, p_E_lo, 512,
        p_WcE_hi, p_WcE_lo, nullptr, nullptr, nullptr, nullptr, 0, nullptr, 320);
    // rel = p0 + p1 + bc -> split
    combine_rel<<<(ROWS * 32 + 255) / 256, 256>>>(bc);

    // G5: [loc|scale|h_out] = rel @ Wstk^T + bstk, final f32 split outputs
    gemm_mma<0,2><<<dim3(6, MB), 256, SMEM_GEMM>>>(
        p_rel_hi, p_rel_lo, 128, 128, nullptr, nullptr, 0,
        p_Wstk_hi, p_Wstk_lo, p_bstk, out1, nullptr, nullptr, 0, out2, 128);
}

// round 16
// speedup vs baseline: 1.1817x; 1.1271x over previous
#include <cuda_runtime.h>
#include <cuda_bf16.h>
#include <math.h>
#include <stdint.h>

#define B_SZ   2048
#define K_OBJ  16
#define ROWS   (B_SZ * K_OBJ)      // 32768
#define NPAIR  120

typedef __nv_bfloat16 bf16;

// ---------------- scratch (device globals; no allocation allowed) ----------------
__device__ __align__(16) bf16 g_z_hi  [(size_t)ROWS * 128];
__device__ __align__(16) bf16 g_z_lo  [(size_t)ROWS * 128];
__device__ __align__(16) bf16 g_h0_hi [(size_t)ROWS * 128];
__device__ __align__(16) bf16 g_h0_lo [(size_t)ROWS * 128];
__device__ __align__(16) bf16 g_ze_hi [(size_t)ROWS * 256];
__device__ __align__(16) bf16 g_ze_lo [(size_t)ROWS * 256];
__device__ __align__(16) bf16 g_h_hi  [(size_t)ROWS * 128];
__device__ __align__(16) bf16 g_h_lo  [(size_t)ROWS * 128];
__device__ __align__(16) bf16 g_E_hi  [(size_t)ROWS * 512];
__device__ __align__(16) bf16 g_E_lo  [(size_t)ROWS * 512];
__device__ __align__(16) bf16 g_rel_hi[(size_t)ROWS * 128];
__device__ __align__(16) bf16 g_rel_lo[(size_t)ROWS * 128];
__device__ __align__(16) float g_gi [(size_t)ROWS * 384];   // also G4 partial0 (ld128)
__device__ __align__(16) float g_gh [(size_t)ROWS * 384];   // also G4 partial1 (ld128)
__device__ __align__(16) float g_UV [(size_t)ROWS * 1024];
__device__ __align__(16) bf16 g_Wobj_hi[256 * 128],  g_Wobj_lo[256 * 128];
__device__ __align__(16) bf16 g_Wih_hi [384 * 256],  g_Wih_lo [384 * 256];
__device__ __align__(16) bf16 g_Whh_hi [384 * 128],  g_Whh_lo [384 * 128];
__device__ __align__(16) bf16 g_WUV_hi [1024 * 128], g_WUV_lo [1024 * 128];
__device__ __align__(16) bf16 g_WcE_hi [128 * 640],  g_WcE_lo [128 * 640];
__device__ __align__(16) bf16 g_Wstk_hi[384 * 128],  g_Wstk_lo[384 * 128];
__device__ __align__(16) float g_bstk[384];
__device__ __align__(16) float g_buv[1024];     // [be/2 | be/2] folded into G3 bias

// ---------------- helpers ----------------
__device__ __forceinline__ void bf16split(float x, bf16& h, bf16& l) {
    h = __float2bfloat16_rn(x);
    l = __float2bfloat16_rn(x - __bfloat162float(h));
}

__device__ __forceinline__ uint32_t smem_u32(const void* p) {
    uint32_t a;
    asm("{ .reg .u64 t; cvta.to.shared.u64 t, %1; cvt.u32.u64 %0, t; }" : "=r"(a) : "l"(p));
    return a;
}

// L1-bypass copy: tiles are consumed once per CTA; keep them out of L1TEX (the binding pipe)
__device__ __forceinline__ void cp16(uint32_t dst, const void* src) {
    asm volatile("cp.async.cg.shared.global [%0], [%1], 16;" :: "r"(dst), "l"(src) : "memory");
}
#define CP_COMMIT() asm volatile("cp.async.commit_group;" ::: "memory")
#define CP_WAIT(n)  asm volatile("cp.async.wait_group %0;" :: "n"(n) : "memory")

__device__ __forceinline__ void mma16(float* d, const uint32_t* a, const uint32_t* b) {
    asm volatile(
        "mma.sync.aligned.m16n8k16.row.col.f32.bf16.bf16.f32 "
        "{%0,%1,%2,%3}, {%4,%5,%6,%7}, {%8,%9}, {%0,%1,%2,%3};"
        : "+f"(d[0]), "+f"(d[1]), "+f"(d[2]), "+f"(d[3])
        : "r"(a[0]), "r"(a[1]), "r"(a[2]), "r"(a[3]), "r"(b[0]), "r"(b[1]));
}

// ---------------- tensor-core bf16x3 NT GEMM, CTA 128x64, 3 CTAs/SM (R12) ----------------
// OUTM: 0 f32 C; 2 final f32 split (C ld256 / C2 ld128);
//       5 G4 split-K (grid.x packs 2 K-halves; raw f32 partials to g_gi/g_gh ld128);
//       6 merged G1(x<4: elu+split->Chi/Clo ld256) / G2b(x>=4: f32->g_gh ld384, bias=C2).
#define PADW 20
#define A_TW  2560   // 128 * PADW
#define B_TW  1280   //  64 * PADW
#define STG_WORDS 7680
#define STG_BYTES (STG_WORDS * 4)

template <int ACT, int OUTM>
__global__ void __launch_bounds__(256, 3) gemm_mma(
    const bf16* __restrict__ X1hi, const bf16* __restrict__ X1lo, int ld1, int k1,
    const bf16* __restrict__ X2hi, const bf16* __restrict__ X2lo, int ld2,
    const bf16* __restrict__ Whi, const bf16* __restrict__ Wlo,
    const float* __restrict__ bias,
    float* __restrict__ C, bf16* __restrict__ Chi, bf16* __restrict__ Clo,
    int ldc, float* __restrict__ C2, int Kd)
{
    extern __shared__ uint32_t smw[];
    const uint32_t sb = smem_u32(smw);

    const int tid = threadIdx.x;
    const int lane = tid & 31;
    const int wid = tid >> 5;
    const int warp_m = wid >> 1;
    const int warp_n = wid & 1;
    const int gid = lane >> 2;
    const int tig = lane & 3;
    const int bm = blockIdx.y * 128;

    int bx = blockIdx.x;
    const bf16 *x1hi = X1hi, *x1lo = X1lo, *x2hi = X2hi, *x2lo = X2lo;
    const bf16 *whi = Whi, *wlo = Wlo;
    const float* biasp = bias;
    int l1 = ld1, l2 = ld2, kb1 = k1, wld = Kd, woff = 0;
    int subq = 0;
    if (OUTM == 5) {
        subq = bx >> 1; bx &= 1;
        wld = 640; biasp = nullptr;
        if (subq == 1) {
            x1hi = g_E_hi + 192; x1lo = g_E_lo + 192; l1 = 512; kb1 = 1 << 30;
            woff = 320;
        }
    }
    if (OUTM == 6) {
        if (bx >= 4) {
            subq = 1; bx -= 4;
            x1hi = g_h0_hi; x1lo = g_h0_lo; l1 = 128; kb1 = 128;
            whi = g_Whh_hi; wlo = g_Whh_lo;
            biasp = (const float*)C2;
        }
    }
    const int bn = bx * 64;

    float acc[2][4][4];
#pragma unroll
    for (int mi = 0; mi < 2; mi++)
#pragma unroll
        for (int nf = 0; nf < 4; nf++)
#pragma unroll
            for (int e = 0; e < 4; e++) acc[mi][nf][e] = 0.f;

    auto load_slab = [&](int k0, int s) {
        const bf16 *ahi, *alo; int xld, xc;
        if (k0 < kb1) { ahi = x1hi; alo = x1lo; xld = l1; xc = k0; }
        else          { ahi = x2hi; alo = x2lo; xld = l2; xc = k0 - kb1; }
        const uint32_t st = sb + s * STG_BYTES;
#pragma unroll
        for (int j = 0; j < 2; j++) {
            int c = tid + j * 256;
            int row = c >> 2, ch = c & 3;
            uint32_t so = (uint32_t)(row * PADW + ch * 4) * 4;
            const size_t ga = (size_t)(bm + row) * xld + xc + ch * 8;
            cp16(st + so,            ahi + ga);
            cp16(st + A_TW * 4 + so, alo + ga);
        }
        {
            int row = tid >> 2, ch = tid & 3;
            uint32_t so = (uint32_t)(row * PADW + ch * 4) * 4;
            const size_t gw = (size_t)(bn + row) * wld + woff + k0 + ch * 8;
            cp16(st + 2 * A_TW * 4 + so,          whi + gw);
            cp16(st + (2 * A_TW + B_TW) * 4 + so, wlo + gw);
        }
    };

    load_slab(0, 0);
    CP_COMMIT();

    const int nIter = Kd >> 5;
#pragma unroll 1
    for (int i = 0; i < nIter; i++) {
        CP_WAIT(0);
        __syncthreads();
        if (i + 1 < nIter) {
            load_slab((i + 1) * 32, (i + 1) & 1);
            CP_COMMIT();
        }

        const uint32_t* sA  = smw + (i & 1) * STG_WORDS;
        const uint32_t* sAl = sA + A_TW;
        const uint32_t* sB  = sA + 2 * A_TW;
        const uint32_t* sBl = sA + 2 * A_TW + B_TW;

#pragma unroll
        for (int h = 0; h < 2; h++) {
            const int kb = h * 8 + tig;
            uint32_t ah[2][4], al[2][4];
#pragma unroll
            for (int mi = 0; mi < 2; mi++) {
                int am = (warp_m * 32 + mi * 16 + gid) * PADW;
                ah[mi][0] = sA [am + kb];
                ah[mi][1] = sA [am + 8 * PADW + kb];
                ah[mi][2] = sA [am + kb + 4];
                ah[mi][3] = sA [am + 8 * PADW + kb + 4];
                al[mi][0] = sAl[am + kb];
                al[mi][1] = sAl[am + 8 * PADW + kb];
                al[mi][2] = sAl[am + kb + 4];
                al[mi][3] = sAl[am + 8 * PADW + kb + 4];
            }
            uint32_t bf[4][2];
#pragma unroll
            for (int nf = 0; nf < 4; nf++) {
                int an = (warp_n * 32 + nf * 8 + gid) * PADW;
                bf[nf][0] = sB[an + kb];
                bf[nf][1] = sB[an + kb + 4];
            }
#pragma unroll
            for (int mi = 0; mi < 2; mi++)
#pragma unroll
                for (int nf = 0; nf < 4; nf++)
                    mma16(acc[mi][nf], ah[mi], bf[nf]);
#pragma unroll
            for (int mi = 0; mi < 2; mi++)
#pragma unroll
                for (int nf = 0; nf < 4; nf++)
                    mma16(acc[mi][nf], al[mi], bf[nf]);
#pragma unroll
            for (int nf = 0; nf < 4; nf++) {
                int an = (warp_n * 32 + nf * 8 + gid) * PADW;
                bf[nf][0] = sBl[an + kb];
                bf[nf][1] = sBl[an + kb + 4];
            }
#pragma unroll
            for (int mi = 0; mi < 2; mi++)
#pragma unroll
                for (int nf = 0; nf < 4; nf++)
                    mma16(acc[mi][nf], ah[mi], bf[nf]);
        }
    }

    // ---- epilogue ----
    float* outp = C; int oldc = ldc, ncol0 = bn;
    bf16 *chip = Chi, *clop = Clo; int sldc = ldc;
    bool splitOut = (OUTM == 1);
    bool doElu = (ACT == 1);
    if (OUTM == 2) {
        if (bn >= 256) { outp = C2; oldc = 128; ncol0 = bn - 256; }
        else           { outp = C;  oldc = 256; ncol0 = bn; }
    }
    if (OUTM == 5) { outp = subq ? g_gh : g_gi; oldc = 128; ncol0 = bn; }
    if (OUTM == 6) {
        if (subq == 0) { splitOut = true; doElu = true; sldc = 256; }
        else           { outp = g_gh; oldc = 384; ncol0 = bn; }
    }

#pragma unroll
    for (int mi = 0; mi < 2; mi++) {
        int r0 = bm + warp_m * 32 + mi * 16 + gid;
#pragma unroll
        for (int nf = 0; nf < 4; nf++) {
            int cg = bn + warp_n * 32 + nf * 8 + tig * 2;
            int cl = ncol0 + warp_n * 32 + nf * 8 + tig * 2;
            float b0 = 0.f, b1 = 0.f;
            if (biasp) { float2 bv = *(const float2*)(biasp + cg); b0 = bv.x; b1 = bv.y; }
            float v00 = acc[mi][nf][0] + b0;
            float v01 = acc[mi][nf][1] + b1;
            float v10 = acc[mi][nf][2] + b0;
            float v11 = acc[mi][nf][3] + b1;
            if (doElu) {
                v00 = (v00 > 0.f) ? v00 : (__expf(v00) - 1.f);
                v01 = (v01 > 0.f) ? v01 : (__expf(v01) - 1.f);
                v10 = (v10 > 0.f) ? v10 : (__expf(v10) - 1.f);
                v11 = (v11 > 0.f) ? v11 : (__expf(v11) - 1.f);
            }
            if (splitOut) {
                bf16 h, l;
                __nv_bfloat162 ph0, pl0, ph1, pl1;
                bf16split(v00, h, l); ph0.x = h; pl0.x = l;
                bf16split(v01, h, l); ph0.y = h; pl0.y = l;
                bf16split(v10, h, l); ph1.x = h; pl1.x = l;
                bf16split(v11, h, l); ph1.y = h; pl1.y = l;
                *(__nv_bfloat162*)(chip + (size_t)r0 * sldc + cl)       = ph0;
                *(__nv_bfloat162*)(clop + (size_t)r0 * sldc + cl)       = pl0;
                *(__nv_bfloat162*)(chip + (size_t)(r0 + 8) * sldc + cl) = ph1;
                *(__nv_bfloat162*)(clop + (size_t)(r0 + 8) * sldc + cl) = pl1;
            } else {
                *(float2*)(outp + (size_t)r0 * oldc + cl)       = make_float2(v00, v01);
                *(float2*)(outp + (size_t)(r0 + 8) * oldc + cl) = make_float2(v10, v11);
            }
        }
    }
}

// ---------------- merged split + weight-fold kernel ----------------
#define N4_Z   1048576
#define N4_H0  1048576
#define N4_WO  8192
#define N4_WIH 24576
#define N4_WHH 12288
#define N4_TOT (N4_Z + N4_H0 + N4_WO + N4_WIH + N4_WHH)
#define N_WUV  131072
#define N_WCE  81920
#define N_WSTK 49152
#define N_ALL  (N4_TOT + N_WUV + N_WCE + N_WSTK + 384 + 1024)

__device__ __forceinline__ void split4(const float4* src, bf16* hi, bf16* lo, int i) {
    float4 v = src[i];
    bf16 h, l;
    __nv_bfloat162 h0, l0, h1, l1;
    bf16split(v.x, h, l); h0.x = h; l0.x = l;
    bf16split(v.y, h, l); h0.y = h; l0.y = l;
    bf16split(v.z, h, l); h1.x = h; l1.x = l;
    bf16split(v.w, h, l); h1.y = h; l1.y = l;
    ((__nv_bfloat162*)hi)[i * 2]     = h0; ((__nv_bfloat162*)lo)[i * 2]     = l0;
    ((__nv_bfloat162*)hi)[i * 2 + 1] = h1; ((__nv_bfloat162*)lo)[i * 2 + 1] = l1;
}

__global__ void splitprep_all(const float* __restrict__ z, const float* __restrict__ h0,
                              const float* __restrict__ W_obj, const float* __restrict__ Wih,
                              const float* __restrict__ Whh,
                              const float* __restrict__ We, const float* __restrict__ Wc,
                              const float* __restrict__ Wl, const float* __restrict__ bl,
                              const float* __restrict__ Wsc, const float* __restrict__ bs,
                              const float* __restrict__ Wh, const float* __restrict__ bh,
                              const float* __restrict__ be) {
    int idx = blockIdx.x * blockDim.x + threadIdx.x;
    if (idx >= N_ALL) return;
    if (idx < N4_Z) { split4((const float4*)z, g_z_hi, g_z_lo, idx); return; }
    if ((idx -= N4_Z) < N4_H0) { split4((const float4*)h0, g_h0_hi, g_h0_lo, idx); return; }
    if ((idx -= N4_H0) < N4_WO) { split4((const float4*)W_obj, g_Wobj_hi, g_Wobj_lo, idx); return; }
    if ((idx -= N4_WO) < N4_WIH) { split4((const float4*)Wih, g_Wih_hi, g_Wih_lo, idx); return; }
    if ((idx -= N4_WIH) < N4_WHH) { split4((const float4*)Whh, g_Whh_hi, g_Whh_lo, idx); return; }
    idx -= N4_WHH;
    if (idx < N_WUV) {
        int n = idx >> 7, c = idx & 127;
        float v;
        if (n < 512) v = We[n * 512 + c] + We[n * 512 + 128 + c];
        else {
            int nn = n - 512;
            v = We[nn * 512 + 256 + c] + We[nn * 512 + 384 + c];
        }
        bf16 h, l; bf16split(v, h, l);
        g_WUV_hi[idx] = h; g_WUV_lo[idx] = l;
    } else if ((idx -= N_WUV) < N_WCE) {
        int n = idx / 640, c = idx % 640;
        float v = (c < 128) ? (Wc[n * 768 + c] + Wc[n * 768 + 128 + c])
                            : Wc[n * 768 + 128 + c];
        bf16 h, l; bf16split(v, h, l);
        g_WcE_hi[idx] = h; g_WcE_lo[idx] = l;
    } else if ((idx -= N_WCE) < N_WSTK) {
        int n = idx >> 7, c = idx & 127;
        const float* W = (n < 128) ? Wl : ((n < 256) ? Wsc : Wh);
        bf16 h, l; bf16split(W[(n & 127) * 128 + c], h, l);
        g_Wstk_hi[idx] = h; g_Wstk_lo[idx] = l;
    } else if ((idx -= N_WSTK) < 384) {
        const float* bb = (idx < 128) ? bl : ((idx < 256) ? bs : bh);
        g_bstk[idx] = bb[idx & 127];
    } else {
        idx -= 384;
        g_buv[idx] = 0.5f * be[idx & 511];
    }
}

// ---------------- GRU gate fusion (float4 vectorized, writes split h) ----------------
__device__ __forceinline__ float sigm(float x) { return 1.f / (1.f + __expf(-x)); }

__global__ void gru_gate(const float* __restrict__ gi, const float* __restrict__ gh,
                         const float* __restrict__ h0,
                         bf16* __restrict__ hhi, bf16* __restrict__ hlo) {
    int idx = blockIdx.x * blockDim.x + threadIdx.x;
    if (idx >= ROWS * 32) return;
    int m = idx >> 5, c4 = (idx & 31) * 4;
    const float* gim = gi + (size_t)m * 384;
    const float* ghm = gh + (size_t)m * 384;
    float4 gir = *(const float4*)(gim + c4);
    float4 giu = *(const float4*)(gim + 128 + c4);
    float4 gin = *(const float4*)(gim + 256 + c4);
    float4 ghr = *(const float4*)(ghm + c4);
    float4 ghu = *(const float4*)(ghm + 128 + c4);
    float4 ghn = *(const float4*)(ghm + 256 + c4);
    float4 h0v = *(const float4*)(h0 + (size_t)m * 128 + c4);
    float out[4];
    {
        float r = sigm(gir.x + ghr.x), u = sigm(giu.x + ghu.x);
        out[0] = (1.f - u) * tanhf(gin.x + r * ghn.x) + u * h0v.x;
        r = sigm(gir.y + ghr.y); u = sigm(giu.y + ghu.y);
        out[1] = (1.f - u) * tanhf(gin.y + r * ghn.y) + u * h0v.y;
        r = sigm(gir.z + ghr.z); u = sigm(giu.z + ghu.z);
        out[2] = (1.f - u) * tanhf(gin.z + r * ghn.z) + u * h0v.z;
        r = sigm(gir.w + ghr.w); u = sigm(giu.w + ghu.w);
        out[3] = (1.f - u) * tanhf(gin.w + r * ghn.w) + u * h0v.w;
    }
    __nv_bfloat162 ph0, pl0, ph1, pl1;
    bf16 h, l;
    bf16split(out[0], h, l); ph0.x = h; pl0.x = l;
    bf16split(out[1], h, l); ph0.y = h; pl0.y = l;
    bf16split(out[2], h, l); ph1.x = h; pl1.x = l;
    bf16split(out[3], h, l); ph1.y = h; pl1.y = l;
    __nv_bfloat162* ho = (__nv_bfloat162*)(hhi + (size_t)m * 128 + c4);
    __nv_bfloat162* lo2 = (__nv_bfloat162*)(hlo + (size_t)m * 128 + c4);
    ho[0] = ph0; ho[1] = ph1;
    lo2[0] = pl0; lo2[1] = pl1;
}

// ---------------- G4 combine: rel = p0 + p1 + bc -> split ----------------
__global__ void combine_rel(const float* __restrict__ bc) {
    int idx = blockIdx.x * blockDim.x + threadIdx.x;
    if (idx >= ROWS * 32) return;
    int m = idx >> 5, c4 = (idx & 31) * 4;
    float4 a = *(const float4*)(g_gi + (size_t)m * 128 + c4);
    float4 b = *(const float4*)(g_gh + (size_t)m * 128 + c4);
    float4 bcv = *(const float4*)(bc + c4);
    float v0 = a.x + b.x + bcv.x;
    float v1 = a.y + b.y + bcv.y;
    float v2 = a.z + b.z + bcv.z;
    float v3 = a.w + b.w + bcv.w;
    __nv_bfloat162 ph0, pl0, ph1, pl1;
    bf16 h, l;
    bf16split(v0, h, l); ph0.x = h; pl0.x = l;
    bf16split(v1, h, l); ph0.y = h; pl0.y = l;
    bf16split(v2, h, l); ph1.x = h; pl1.x = l;
    bf16split(v3, h, l); ph1.y = h; pl1.y = l;
    __nv_bfloat162* ho = (__nv_bfloat162*)(g_rel_hi + (size_t)m * 128 + c4);
    __nv_bfloat162* lo2 = (__nv_bfloat162*)(g_rel_lo + (size_t)m * 128 + c4);
    ho[0] = ph0; ho[1] = ph1;
    lo2[0] = pl0; lo2[1] = pl1;
}

// ---------------- pair stage: 2 warps/object, 1024 threads, 8 barriers ----------------
// Processes two partner objects per __syncthreads(); dot-exchange slots double-buffered
// on (o>>1)&1 (buffer reuse distance = 2 syncs => race-free). Math identical to R15.
__global__ void __launch_bounds__(1024, 1) pair_kernel(
    const float* __restrict__ UV, const float* __restrict__ Wa,
    const float* __restrict__ ba,
    bf16* __restrict__ Ehi, bf16* __restrict__ Elo)
{
    extern __shared__ float smf[];
    float* Ub   = smf;                  // 16*512
    float* Vb   = Ub + 16 * 512;        // 16*512
    float* dotp = Vb + 16 * 512;        // 2 bufs * 2 objs * 32 warps = 128

    const int b = blockIdx.x;
    const int tid = threadIdx.x;
    const int wid = tid >> 5, lane = tid & 31;
    const int objw = wid & 15;
    const int half = wid >> 4;
    const int cbase = half * 256 + lane;

    for (int i = tid; i < 4096; i += 1024) {
        int k = i >> 8, t4 = i & 255;
        float4 v = *(const float4*)(UV + ((size_t)(b * 16 + k)) * 1024 + t4 * 4);
        float* dst = (t4 < 128) ? (Ub + k * 512 + t4 * 4)
                                : (Vb + k * 512 + (t4 - 128) * 4);
        *(float4*)dst = v;
    }
    __syncthreads();

    const float ba0 = __ldg(&ba[0]);
    float uw[8], vw[8], war[8], Ew[8];
#pragma unroll
    for (int c = 0; c < 8; c++) {
        int t = cbase + 32 * c;
        uw[c] = Ub[objw * 512 + t];
        vw[c] = Vb[objw * 512 + t];
        war[c] = __ldg(&Wa[t]);
        Ew[c] = 0.f;
    }

#pragma unroll 1
    for (int o = 0; o < K_OBJ; o += 2) {
        float e1[8], e2[8];
        float dot1 = 0.f, dot2 = 0.f;
        const bool act1 = (o != objw);
        const bool act2 = (o + 1 != objw);
        if (act1) {
            if (o > objw) {
                const float* Vrow = Vb + o * 512;
#pragma unroll
                for (int c = 0; c < 8; c++) {
                    float x = uw[c] + Vrow[cbase + 32 * c];
                    x = (x > 0.f) ? x : (__expf(x) - 1.f);
                    e1[c] = x; dot1 += x * war[c];
                }
            } else {
                const float* Urow = Ub + o * 512;
#pragma unroll
                for (int c = 0; c < 8; c++) {
                    float x = Urow[cbase + 32 * c] + vw[c];
                    x = (x > 0.f) ? x : (__expf(x) - 1.f);
                    e1[c] = x; dot1 += x * war[c];
                }
            }
#pragma unroll
            for (int off = 16; off > 0; off >>= 1) dot1 += __shfl_xor_sync(0xffffffffu, dot1, off);
        }
        if (act2) {
            if (o + 1 > objw) {
                const float* Vrow = Vb + (o + 1) * 512;
#pragma unroll
                for (int c = 0; c < 8; c++) {
                    float x = uw[c] + Vrow[cbase + 32 * c];
                    x = (x > 0.f) ? x : (__expf(x) - 1.f);
                    e2[c] = x; dot2 += x * war[c];
                }
            } else {
                const float* Urow = Ub + (o + 1) * 512;
#pragma unroll
                for (int c = 0; c < 8; c++) {
                    float x = Urow[cbase + 32 * c] + vw[c];
                    x = (x > 0.f) ? x : (__expf(x) - 1.f);
                    e2[c] = x; dot2 += x * war[c];
                }
            }
#pragma unroll
            for (int off = 16; off > 0; off >>= 1) dot2 += __shfl_xor_sync(0xffffffffu, dot2, off);
        }
        const int buf = ((o >> 1) & 1) * 64;
        if (lane == 0) { dotp[buf + wid] = dot1; dotp[buf + 32 + wid] = dot2; }
        __syncthreads();
        if (act1) {
            float dsum = dot1 + dotp[buf + (wid ^ 16)];
            float att = 1.f / (1.f + __expf(-(dsum + ba0)));
#pragma unroll
            for (int c = 0; c < 8; c++) Ew[c] += att * e1[c];
        }
        if (act2) {
            float dsum = dot2 + dotp[buf + 32 + (wid ^ 16)];
            float att = 1.f / (1.f + __expf(-(dsum + ba0)));
#pragma unroll
            for (int c = 0; c < 8; c++) Ew[c] += att * e2[c];
        }
    }

    bf16* Eh = Ehi + ((size_t)b * 16 + objw) * 512;
    bf16* El = Elo + ((size_t)b * 16 + objw) * 512;
#pragma unroll
    for (int c = 0; c < 8; c++) {
        bf16 h, l; bf16split(Ew[c], h, l);
        Eh[cbase + 32 * c] = h;
        El[cbase + 32 * c] = l;
    }
}

// ---------------- host launcher ----------------
extern "C" void kernel_launch(void* const* d_in, const int* in_sizes, int n_in,
                              void* d_out, int out_size)
{
    const float* z    = (const float*)d_in[0];
    const float* h0   = (const float*)d_in[1];
    const float* W_obj= (const float*)d_in[2];
    const float* b_obj= (const float*)d_in[3];
    const float* Wih  = (const float*)d_in[4];
    const float* bih  = (const float*)d_in[5];
    const float* Whh  = (const float*)d_in[6];
    const float* bhh  = (const float*)d_in[7];
    const float* We   = (const float*)d_in[8];
    const float* be   = (const float*)d_in[9];
    const float* Wa   = (const float*)d_in[10];
    const float* ba   = (const float*)d_in[11];
    const float* Wc   = (const float*)d_in[12];
    const float* bc   = (const float*)d_in[13];
    const float* Wl   = (const float*)d_in[14];
    const float* bl   = (const float*)d_in[15];
    const float* Wsc  = (const float*)d_in[16];
    const float* bs   = (const float*)d_in[17];
    const float* Wh   = (const float*)d_in[18];
    const float* bh   = (const float*)d_in[19];

    float* out1 = (float*)d_out;
    float* out2 = out1 + (size_t)ROWS * 256;

    bf16 *p_z_hi, *p_z_lo, *p_ze_hi, *p_ze_lo;
    bf16 *p_h_hi, *p_h_lo, *p_E_hi, *p_E_lo, *p_rel_hi, *p_rel_lo;
    float *p_gi, *p_gh, *p_UV, *p_bstk, *p_buv;
    bf16 *p_Wobj_hi, *p_Wobj_lo, *p_Wih_hi, *p_Wih_lo;
    bf16 *p_WUV_hi, *p_WUV_lo, *p_WcE_hi, *p_WcE_lo, *p_Wstk_hi, *p_Wstk_lo;

    cudaGetSymbolAddress((void**)&p_z_hi,  g_z_hi);   cudaGetSymbolAddress((void**)&p_z_lo,  g_z_lo);
    cudaGetSymbolAddress((void**)&p_ze_hi, g_ze_hi);  cudaGetSymbolAddress((void**)&p_ze_lo, g_ze_lo);
    cudaGetSymbolAddress((void**)&p_h_hi,  g_h_hi);   cudaGetSymbolAddress((void**)&p_h_lo,  g_h_lo);
    cudaGetSymbolAddress((void**)&p_E_hi,  g_E_hi);   cudaGetSymbolAddress((void**)&p_E_lo,  g_E_lo);
    cudaGetSymbolAddress((void**)&p_rel_hi,g_rel_hi); cudaGetSymbolAddress((void**)&p_rel_lo,g_rel_lo);
    cudaGetSymbolAddress((void**)&p_gi, g_gi);
    cudaGetSymbolAddress((void**)&p_gh, g_gh);
    cudaGetSymbolAddress((void**)&p_UV, g_UV);
    cudaGetSymbolAddress((void**)&p_bstk, g_bstk);
    cudaGetSymbolAddress((void**)&p_buv, g_buv);
    cudaGetSymbolAddress((void**)&p_Wobj_hi, g_Wobj_hi); cudaGetSymbolAddress((void**)&p_Wobj_lo, g_Wobj_lo);
    cudaGetSymbolAddress((void**)&p_Wih_hi,  g_Wih_hi);  cudaGetSymbolAddress((void**)&p_Wih_lo,  g_Wih_lo);
    cudaGetSymbolAddress((void**)&p_WUV_hi,  g_WUV_hi);  cudaGetSymbolAddress((void**)&p_WUV_lo,  g_WUV_lo);
    cudaGetSymbolAddress((void**)&p_WcE_hi,  g_WcE_hi);  cudaGetSymbolAddress((void**)&p_WcE_lo,  g_WcE_lo);
    cudaGetSymbolAddress((void**)&p_Wstk_hi, g_Wstk_hi); cudaGetSymbolAddress((void**)&p_Wstk_lo, g_Wstk_lo);

    const int SMEM_GEMM = 2 * STG_BYTES;   // 61440
    cudaFuncSetAttribute(gemm_mma<0,6>, cudaFuncAttributeMaxDynamicSharedMemorySize, SMEM_GEMM);
    cudaFuncSetAttribute(gemm_mma<0,0>, cudaFuncAttributeMaxDynamicSharedMemorySize, SMEM_GEMM);
    cudaFuncSetAttribute(gemm_mma<0,5>, cudaFuncAttributeMaxDynamicSharedMemorySize, SMEM_GEMM);
    cudaFuncSetAttribute(gemm_mma<0,2>, cudaFuncAttributeMaxDynamicSharedMemorySize, SMEM_GEMM);

    splitprep_all<<<(N_ALL + 255) / 256, 256>>>(z, h0, W_obj, Wih, Whh,
                                                We, Wc, Wl, bl, Wsc, bs, Wh, bh, be);

    const int MB = ROWS / 128;   // 256

    // G1 (x<4: z_embed = elu(z@Wobj^T+b_obj) -> ze split) + G2b (x>=4: gh = h0@Whh^T+bhh)
    gemm_mma<0,6><<<dim3(10, MB), 256, SMEM_GEMM>>>(
        p_z_hi, p_z_lo, 128, 128, nullptr, nullptr, 0,
        p_Wobj_hi, p_Wobj_lo, b_obj, nullptr, p_ze_hi, p_ze_lo, 256, (float*)bhh, 128);

    // G2a: gi = z_embed @ Wih^T + bih  [ROWS, 384] f32
    gemm_mma<0,0><<<dim3(6, MB), 256, SMEM_GEMM>>>(
        p_ze_hi, p_ze_lo, 256, 256, nullptr, nullptr, 0,
        p_Wih_hi, p_Wih_lo, bih, p_gi, nullptr, nullptr, 384, nullptr, 256);

    // GRU gates -> h (split)
    gru_gate<<<(ROWS * 32 + 255) / 256, 256>>>(p_gi, p_gh, h0, p_h_hi, p_h_lo);

    // G3: UV = h @ W_UV^T + [be/2 | be/2]  [ROWS, 1024] f32
    gemm_mma<0,0><<<dim3(16, MB), 256, SMEM_GEMM>>>(
        p_h_hi, p_h_lo, 128, 128, nullptr, nullptr, 0,
        p_WUV_hi, p_WUV_lo, p_buv, p_UV, nullptr, nullptr, 1024, nullptr, 128);

    // pair stage -> E (split) [ROWS, 512]
    size_t psmem = (2 * 16 * 512 + 128) * sizeof(float);
    cudaFuncSetAttribute(pair_kernel, cudaFuncAttributeMaxDynamicSharedMemorySize, (int)psmem);
    pair_kernel<<<B_SZ, 1024, psmem>>>(p_UV, Wa, ba, p_E_hi, p_E_lo);

    // G4: split-K x2 in one launch (Kd=320 per half); partials -> g_gi / g_gh
    gemm_mma<0,5><<<dim3(4, MB), 256, SMEM_GEMM>>>(
        p_h_hi, p_h_lo, 128, 128, p_E_hi, p_E_lo, 512,
        p_WcE_hi, p_WcE_lo, nullptr, nullptr, nullptr, nullptr, 0, nullptr, 320);
    combine_rel<<<(ROWS * 32 + 255) / 256, 256>>>(bc);

    // G5: [loc|scale|h_out] = rel @ Wstk^T + bstk, final f32 split outputs
    gemm_mma<0,2><<<dim3(6, MB), 256, SMEM_GEMM>>>(
        p_rel_hi, p_rel_lo, 128, 128, nullptr, nullptr, 0,
        p_Wstk_hi, p_Wstk_lo, p_bstk, out1, nullptr, nullptr, 0, out2, 128);
}

// round 17
// speedup vs baseline: 1.2114x; 1.0251x over previous
#include <cuda_runtime.h>
#include <cuda_bf16.h>
#include <math.h>
#include <stdint.h>

#define B_SZ   2048
#define K_OBJ  16
#define ROWS   (B_SZ * K_OBJ)      // 32768
#define NPAIR  120

typedef __nv_bfloat16 bf16;

// ---------------- scratch (device globals; no allocation allowed) ----------------
__device__ __align__(16) bf16 g_z_hi  [(size_t)ROWS * 128];
__device__ __align__(16) bf16 g_z_lo  [(size_t)ROWS * 128];
__device__ __align__(16) bf16 g_h0_hi [(size_t)ROWS * 128];
__device__ __align__(16) bf16 g_h0_lo [(size_t)ROWS * 128];
__device__ __align__(16) bf16 g_ze_hi [(size_t)ROWS * 256];
__device__ __align__(16) bf16 g_ze_lo [(size_t)ROWS * 256];
__device__ __align__(16) bf16 g_h_hi  [(size_t)ROWS * 128];
__device__ __align__(16) bf16 g_h_lo  [(size_t)ROWS * 128];
__device__ __align__(16) bf16 g_E_hi  [(size_t)ROWS * 512];
__device__ __align__(16) bf16 g_E_lo  [(size_t)ROWS * 512];
__device__ __align__(16) bf16 g_rel_hi[(size_t)ROWS * 128];
__device__ __align__(16) bf16 g_rel_lo[(size_t)ROWS * 128];
__device__ __align__(16) float g_gi [(size_t)ROWS * 384];   // also G4 partial0 (ld128)
__device__ __align__(16) float g_gh [(size_t)ROWS * 384];   // also G4 partial1 (ld128)
__device__ __align__(16) float g_UV [(size_t)ROWS * 1024];
__device__ __align__(16) bf16 g_Wobj_hi[256 * 128],  g_Wobj_lo[256 * 128];
__device__ __align__(16) bf16 g_Wih_hi [384 * 256],  g_Wih_lo [384 * 256];
__device__ __align__(16) bf16 g_Whh_hi [384 * 128],  g_Whh_lo [384 * 128];
__device__ __align__(16) bf16 g_WUV_hi [1024 * 128], g_WUV_lo [1024 * 128];
__device__ __align__(16) bf16 g_WcE_hi [128 * 640],  g_WcE_lo [128 * 640];
__device__ __align__(16) bf16 g_Wstk_hi[384 * 128],  g_Wstk_lo[384 * 128];
__device__ __align__(16) float g_bstk[384];
__device__ __align__(16) float g_buv[1024];     // [be/2 | be/2] folded into G3 bias

// ---------------- helpers ----------------
__device__ __forceinline__ void bf16split(float x, bf16& h, bf16& l) {
    h = __float2bfloat16_rn(x);
    l = __float2bfloat16_rn(x - __bfloat162float(h));
}

__device__ __forceinline__ uint32_t smem_u32(const void* p) {
    uint32_t a;
    asm("{ .reg .u64 t; cvta.to.shared.u64 t, %1; cvt.u32.u64 %0, t; }" : "=r"(a) : "l"(p));
    return a;
}

// L1-bypass copy: tiles are consumed once per CTA; keep them out of L1TEX (the binding pipe)
__device__ __forceinline__ void cp16(uint32_t dst, const void* src) {
    asm volatile("cp.async.cg.shared.global [%0], [%1], 16;" :: "r"(dst), "l"(src) : "memory");
}
#define CP_COMMIT() asm volatile("cp.async.commit_group;" ::: "memory")
#define CP_WAIT(n)  asm volatile("cp.async.wait_group %0;" :: "n"(n) : "memory")

__device__ __forceinline__ void mma16(float* d, const uint32_t* a, const uint32_t* b) {
    asm volatile(
        "mma.sync.aligned.m16n8k16.row.col.f32.bf16.bf16.f32 "
        "{%0,%1,%2,%3}, {%4,%5,%6,%7}, {%8,%9}, {%0,%1,%2,%3};"
        : "+f"(d[0]), "+f"(d[1]), "+f"(d[2]), "+f"(d[3])
        : "r"(a[0]), "r"(a[1]), "r"(a[2]), "r"(a[3]), "r"(b[0]), "r"(b[1]));
}

// ---------------- tensor-core bf16x3 NT GEMM, CTA 128x64, 3 CTAs/SM (R12) ----------------
// OUTM: 0 f32 C; 2 final f32 split (C ld256 / C2 ld128);
//       5 G4 split-K (grid.x packs 2 K-halves; raw f32 partials to g_gi/g_gh ld128);
//       6 merged G1(x<4: elu+split->Chi/Clo ld256) / G2b(x>=4: f32->g_gh ld384, bias=C2).
#define PADW 20
#define A_TW  2560   // 128 * PADW
#define B_TW  1280   //  64 * PADW
#define STG_WORDS 7680
#define STG_BYTES (STG_WORDS * 4)

template <int ACT, int OUTM>
__global__ void __launch_bounds__(256, 3) gemm_mma(
    const bf16* __restrict__ X1hi, const bf16* __restrict__ X1lo, int ld1, int k1,
    const bf16* __restrict__ X2hi, const bf16* __restrict__ X2lo, int ld2,
    const bf16* __restrict__ Whi, const bf16* __restrict__ Wlo,
    const float* __restrict__ bias,
    float* __restrict__ C, bf16* __restrict__ Chi, bf16* __restrict__ Clo,
    int ldc, float* __restrict__ C2, int Kd)
{
    extern __shared__ uint32_t smw[];
    const uint32_t sb = smem_u32(smw);

    const int tid = threadIdx.x;
    const int lane = tid & 31;
    const int wid = tid >> 5;
    const int warp_m = wid >> 1;
    const int warp_n = wid & 1;
    const int gid = lane >> 2;
    const int tig = lane & 3;
    const int bm = blockIdx.y * 128;

    int bx = blockIdx.x;
    const bf16 *x1hi = X1hi, *x1lo = X1lo, *x2hi = X2hi, *x2lo = X2lo;
    const bf16 *whi = Whi, *wlo = Wlo;
    const float* biasp = bias;
    int l1 = ld1, l2 = ld2, kb1 = k1, wld = Kd, woff = 0;
    int subq = 0;
    if (OUTM == 5) {
        subq = bx >> 1; bx &= 1;
        wld = 640; biasp = nullptr;
        if (subq == 1) {
            x1hi = g_E_hi + 192; x1lo = g_E_lo + 192; l1 = 512; kb1 = 1 << 30;
            woff = 320;
        }
    }
    if (OUTM == 6) {
        if (bx >= 4) {
            subq = 1; bx -= 4;
            x1hi = g_h0_hi; x1lo = g_h0_lo; l1 = 128; kb1 = 128;
            whi = g_Whh_hi; wlo = g_Whh_lo;
            biasp = (const float*)C2;
        }
    }
    const int bn = bx * 64;

    float acc[2][4][4];
#pragma unroll
    for (int mi = 0; mi < 2; mi++)
#pragma unroll
        for (int nf = 0; nf < 4; nf++)
#pragma unroll
            for (int e = 0; e < 4; e++) acc[mi][nf][e] = 0.f;

    auto load_slab = [&](int k0, int s) {
        const bf16 *ahi, *alo; int xld, xc;
        if (k0 < kb1) { ahi = x1hi; alo = x1lo; xld = l1; xc = k0; }
        else          { ahi = x2hi; alo = x2lo; xld = l2; xc = k0 - kb1; }
        const uint32_t st = sb + s * STG_BYTES;
#pragma unroll
        for (int j = 0; j < 2; j++) {
            int c = tid + j * 256;
            int row = c >> 2, ch = c & 3;
            uint32_t so = (uint32_t)(row * PADW + ch * 4) * 4;
            const size_t ga = (size_t)(bm + row) * xld + xc + ch * 8;
            cp16(st + so,            ahi + ga);
            cp16(st + A_TW * 4 + so, alo + ga);
        }
        {
            int row = tid >> 2, ch = tid & 3;
            uint32_t so = (uint32_t)(row * PADW + ch * 4) * 4;
            const size_t gw = (size_t)(bn + row) * wld + woff + k0 + ch * 8;
            cp16(st + 2 * A_TW * 4 + so,          whi + gw);
            cp16(st + (2 * A_TW + B_TW) * 4 + so, wlo + gw);
        }
    };

    load_slab(0, 0);
    CP_COMMIT();

    const int nIter = Kd >> 5;
#pragma unroll 1
    for (int i = 0; i < nIter; i++) {
        CP_WAIT(0);
        __syncthreads();
        if (i + 1 < nIter) {
            load_slab((i + 1) * 32, (i + 1) & 1);
            CP_COMMIT();
        }

        const uint32_t* sA  = smw + (i & 1) * STG_WORDS;
        const uint32_t* sAl = sA + A_TW;
        const uint32_t* sB  = sA + 2 * A_TW;
        const uint32_t* sBl = sA + 2 * A_TW + B_TW;

#pragma unroll
        for (int h = 0; h < 2; h++) {
            const int kb = h * 8 + tig;
            uint32_t ah[2][4], al[2][4];
#pragma unroll
            for (int mi = 0; mi < 2; mi++) {
                int am = (warp_m * 32 + mi * 16 + gid) * PADW;
                ah[mi][0] = sA [am + kb];
                ah[mi][1] = sA [am + 8 * PADW + kb];
                ah[mi][2] = sA [am + kb + 4];
                ah[mi][3] = sA [am + 8 * PADW + kb + 4];
                al[mi][0] = sAl[am + kb];
                al[mi][1] = sAl[am + 8 * PADW + kb];
                al[mi][2] = sAl[am + kb + 4];
                al[mi][3] = sAl[am + 8 * PADW + kb + 4];
            }
            uint32_t bf[4][2];
#pragma unroll
            for (int nf = 0; nf < 4; nf++) {
                int an = (warp_n * 32 + nf * 8 + gid) * PADW;
                bf[nf][0] = sB[an + kb];
                bf[nf][1] = sB[an + kb + 4];
            }
#pragma unroll
            for (int mi = 0; mi < 2; mi++)
#pragma unroll
                for (int nf = 0; nf < 4; nf++)
                    mma16(acc[mi][nf], ah[mi], bf[nf]);
#pragma unroll
            for (int mi = 0; mi < 2; mi++)
#pragma unroll
                for (int nf = 0; nf < 4; nf++)
                    mma16(acc[mi][nf], al[mi], bf[nf]);
#pragma unroll
            for (int nf = 0; nf < 4; nf++) {
                int an = (warp_n * 32 + nf * 8 + gid) * PADW;
                bf[nf][0] = sBl[an + kb];
                bf[nf][1] = sBl[an + kb + 4];
            }
#pragma unroll
            for (int mi = 0; mi < 2; mi++)
#pragma unroll
                for (int nf = 0; nf < 4; nf++)
                    mma16(acc[mi][nf], ah[mi], bf[nf]);
        }
    }

    // ---- epilogue ----
    float* outp = C; int oldc = ldc, ncol0 = bn;
    bf16 *chip = Chi, *clop = Clo; int sldc = ldc;
    bool splitOut = (OUTM == 1);
    bool doElu = (ACT == 1);
    if (OUTM == 2) {
        if (bn >= 256) { outp = C2; oldc = 128; ncol0 = bn - 256; }
        else           { outp = C;  oldc = 256; ncol0 = bn; }
    }
    if (OUTM == 5) { outp = subq ? g_gh : g_gi; oldc = 128; ncol0 = bn; }
    if (OUTM == 6) {
        if (subq == 0) { splitOut = true; doElu = true; sldc = 256; }
        else           { outp = g_gh; oldc = 384; ncol0 = bn; }
    }

#pragma unroll
    for (int mi = 0; mi < 2; mi++) {
        int r0 = bm + warp_m * 32 + mi * 16 + gid;
#pragma unroll
        for (int nf = 0; nf < 4; nf++) {
            int cg = bn + warp_n * 32 + nf * 8 + tig * 2;
            int cl = ncol0 + warp_n * 32 + nf * 8 + tig * 2;
            float b0 = 0.f, b1 = 0.f;
            if (biasp) { float2 bv = *(const float2*)(biasp + cg); b0 = bv.x; b1 = bv.y; }
            float v00 = acc[mi][nf][0] + b0;
            float v01 = acc[mi][nf][1] + b1;
            float v10 = acc[mi][nf][2] + b0;
            float v11 = acc[mi][nf][3] + b1;
            if (doElu) {
                v00 = (v00 > 0.f) ? v00 : (__expf(v00) - 1.f);
                v01 = (v01 > 0.f) ? v01 : (__expf(v01) - 1.f);
                v10 = (v10 > 0.f) ? v10 : (__expf(v10) - 1.f);
                v11 = (v11 > 0.f) ? v11 : (__expf(v11) - 1.f);
            }
            if (splitOut) {
                bf16 h, l;
                __nv_bfloat162 ph0, pl0, ph1, pl1;
                bf16split(v00, h, l); ph0.x = h; pl0.x = l;
                bf16split(v01, h, l); ph0.y = h; pl0.y = l;
                bf16split(v10, h, l); ph1.x = h; pl1.x = l;
                bf16split(v11, h, l); ph1.y = h; pl1.y = l;
                *(__nv_bfloat162*)(chip + (size_t)r0 * sldc + cl)       = ph0;
                *(__nv_bfloat162*)(clop + (size_t)r0 * sldc + cl)       = pl0;
                *(__nv_bfloat162*)(chip + (size_t)(r0 + 8) * sldc + cl) = ph1;
                *(__nv_bfloat162*)(clop + (size_t)(r0 + 8) * sldc + cl) = pl1;
            } else {
                *(float2*)(outp + (size_t)r0 * oldc + cl)       = make_float2(v00, v01);
                *(float2*)(outp + (size_t)(r0 + 8) * oldc + cl) = make_float2(v10, v11);
            }
        }
    }
}

// ---------------- merged split + weight-fold kernel ----------------
#define N4_Z   1048576
#define N4_H0  1048576
#define N4_WO  8192
#define N4_WIH 24576
#define N4_WHH 12288
#define N4_TOT (N4_Z + N4_H0 + N4_WO + N4_WIH + N4_WHH)
#define N_WUV  131072
#define N_WCE  81920
#define N_WSTK 49152
#define N_ALL  (N4_TOT + N_WUV + N_WCE + N_WSTK + 384 + 1024)

__device__ __forceinline__ void split4(const float4* src, bf16* hi, bf16* lo, int i) {
    float4 v = src[i];
    bf16 h, l;
    __nv_bfloat162 h0, l0, h1, l1;
    bf16split(v.x, h, l); h0.x = h; l0.x = l;
    bf16split(v.y, h, l); h0.y = h; l0.y = l;
    bf16split(v.z, h, l); h1.x = h; l1.x = l;
    bf16split(v.w, h, l); h1.y = h; l1.y = l;
    ((__nv_bfloat162*)hi)[i * 2]     = h0; ((__nv_bfloat162*)lo)[i * 2]     = l0;
    ((__nv_bfloat162*)hi)[i * 2 + 1] = h1; ((__nv_bfloat162*)lo)[i * 2 + 1] = l1;
}

__global__ void splitprep_all(const float* __restrict__ z, const float* __restrict__ h0,
                              const float* __restrict__ W_obj, const float* __restrict__ Wih,
                              const float* __restrict__ Whh,
                              const float* __restrict__ We, const float* __restrict__ Wc,
                              const float* __restrict__ Wl, const float* __restrict__ bl,
                              const float* __restrict__ Wsc, const float* __restrict__ bs,
                              const float* __restrict__ Wh, const float* __restrict__ bh,
                              const float* __restrict__ be) {
    int idx = blockIdx.x * blockDim.x + threadIdx.x;
    if (idx >= N_ALL) return;
    if (idx < N4_Z) { split4((const float4*)z, g_z_hi, g_z_lo, idx); return; }
    if ((idx -= N4_Z) < N4_H0) { split4((const float4*)h0, g_h0_hi, g_h0_lo, idx); return; }
    if ((idx -= N4_H0) < N4_WO) { split4((const float4*)W_obj, g_Wobj_hi, g_Wobj_lo, idx); return; }
    if ((idx -= N4_WO) < N4_WIH) { split4((const float4*)Wih, g_Wih_hi, g_Wih_lo, idx); return; }
    if ((idx -= N4_WIH) < N4_WHH) { split4((const float4*)Whh, g_Whh_hi, g_Whh_lo, idx); return; }
    idx -= N4_WHH;
    if (idx < N_WUV) {
        int n = idx >> 7, c = idx & 127;
        float v;
        if (n < 512) v = We[n * 512 + c] + We[n * 512 + 128 + c];
        else {
            int nn = n - 512;
            v = We[nn * 512 + 256 + c] + We[nn * 512 + 384 + c];
        }
        bf16 h, l; bf16split(v, h, l);
        g_WUV_hi[idx] = h; g_WUV_lo[idx] = l;
    } else if ((idx -= N_WUV) < N_WCE) {
        int n = idx / 640, c = idx % 640;
        float v = (c < 128) ? (Wc[n * 768 + c] + Wc[n * 768 + 128 + c])
                            : Wc[n * 768 + 128 + c];
        bf16 h, l; bf16split(v, h, l);
        g_WcE_hi[idx] = h; g_WcE_lo[idx] = l;
    } else if ((idx -= N_WCE) < N_WSTK) {
        int n = idx >> 7, c = idx & 127;
        const float* W = (n < 128) ? Wl : ((n < 256) ? Wsc : Wh);
        bf16 h, l; bf16split(W[(n & 127) * 128 + c], h, l);
        g_Wstk_hi[idx] = h; g_Wstk_lo[idx] = l;
    } else if ((idx -= N_WSTK) < 384) {
        const float* bb = (idx < 128) ? bl : ((idx < 256) ? bs : bh);
        g_bstk[idx] = bb[idx & 127];
    } else {
        idx -= 384;
        g_buv[idx] = 0.5f * be[idx & 511];
    }
}

// ---------------- GRU gate fusion (float4 vectorized, writes split h) ----------------
__device__ __forceinline__ float sigm(float x) { return 1.f / (1.f + __expf(-x)); }

__global__ void gru_gate(const float* __restrict__ gi, const float* __restrict__ gh,
                         const float* __restrict__ h0,
                         bf16* __restrict__ hhi, bf16* __restrict__ hlo) {
    int idx = blockIdx.x * blockDim.x + threadIdx.x;
    if (idx >= ROWS * 32) return;
    int m = idx >> 5, c4 = (idx & 31) * 4;
    const float* gim = gi + (size_t)m * 384;
    const float* ghm = gh + (size_t)m * 384;
    float4 gir = *(const float4*)(gim + c4);
    float4 giu = *(const float4*)(gim + 128 + c4);
    float4 gin = *(const float4*)(gim + 256 + c4);
    float4 ghr = *(const float4*)(ghm + c4);
    float4 ghu = *(const float4*)(ghm + 128 + c4);
    float4 ghn = *(const float4*)(ghm + 256 + c4);
    float4 h0v = *(const float4*)(h0 + (size_t)m * 128 + c4);
    float out[4];
    {
        float r = sigm(gir.x + ghr.x), u = sigm(giu.x + ghu.x);
        out[0] = (1.f - u) * tanhf(gin.x + r * ghn.x) + u * h0v.x;
        r = sigm(gir.y + ghr.y); u = sigm(giu.y + ghu.y);
        out[1] = (1.f - u) * tanhf(gin.y + r * ghn.y) + u * h0v.y;
        r = sigm(gir.z + ghr.z); u = sigm(giu.z + ghu.z);
        out[2] = (1.f - u) * tanhf(gin.z + r * ghn.z) + u * h0v.z;
        r = sigm(gir.w + ghr.w); u = sigm(giu.w + ghu.w);
        out[3] = (1.f - u) * tanhf(gin.w + r * ghn.w) + u * h0v.w;
    }
    __nv_bfloat162 ph0, pl0, ph1, pl1;
    bf16 h, l;
    bf16split(out[0], h, l); ph0.x = h; pl0.x = l;
    bf16split(out[1], h, l); ph0.y = h; pl0.y = l;
    bf16split(out[2], h, l); ph1.x = h; pl1.x = l;
    bf16split(out[3], h, l); ph1.y = h; pl1.y = l;
    __nv_bfloat162* ho = (__nv_bfloat162*)(hhi + (size_t)m * 128 + c4);
    __nv_bfloat162* lo2 = (__nv_bfloat162*)(hlo + (size_t)m * 128 + c4);
    ho[0] = ph0; ho[1] = ph1;
    lo2[0] = pl0; lo2[1] = pl1;
}

// ---------------- G4 combine: rel = p0 + p1 + bc -> split ----------------
__global__ void combine_rel(const float* __restrict__ bc) {
    int idx = blockIdx.x * blockDim.x + threadIdx.x;
    if (idx >= ROWS * 32) return;
    int m = idx >> 5, c4 = (idx & 31) * 4;
    float4 a = *(const float4*)(g_gi + (size_t)m * 128 + c4);
    float4 b = *(const float4*)(g_gh + (size_t)m * 128 + c4);
    float4 bcv = *(const float4*)(bc + c4);
    float v0 = a.x + b.x + bcv.x;
    float v1 = a.y + b.y + bcv.y;
    float v2 = a.z + b.z + bcv.z;
    float v3 = a.w + b.w + bcv.w;
    __nv_bfloat162 ph0, pl0, ph1, pl1;
    bf16 h, l;
    bf16split(v0, h, l); ph0.x = h; pl0.x = l;
    bf16split(v1, h, l); ph0.y = h; pl0.y = l;
    bf16split(v2, h, l); ph1.x = h; pl1.x = l;
    bf16split(v3, h, l); ph1.y = h; pl1.y = l;
    __nv_bfloat162* ho = (__nv_bfloat162*)(g_rel_hi + (size_t)m * 128 + c4);
    __nv_bfloat162* lo2 = (__nv_bfloat162*)(g_rel_lo + (size_t)m * 128 + c4);
    ho[0] = ph0; ho[1] = ph1;
    lo2[0] = pl0; lo2[1] = pl1;
}

// ---------------- pair stage: 2 warps/object, pairwise named barriers ----------------
// Dot-exchange couples only warps (w, w^16): use bar.sync objw, 64 instead of CTA-wide
// __syncthreads (named barrier drains pending STS for the 2 participating warps).
// Double-buffered slots on (o>>1)&1 keep write-after-read distance = 2 barriers.
__global__ void __launch_bounds__(1024, 1) pair_kernel(
    const float* __restrict__ UV, const float* __restrict__ Wa,
    const float* __restrict__ ba,
    bf16* __restrict__ Ehi, bf16* __restrict__ Elo)
{
    extern __shared__ float smf[];
    float* Ub   = smf;                  // 16*512
    float* Vb   = Ub + 16 * 512;        // 16*512
    float* dotp = Vb + 16 * 512;        // 2 bufs * 2 objs * 32 warps = 128

    const int b = blockIdx.x;
    const int tid = threadIdx.x;
    const int wid = tid >> 5, lane = tid & 31;
    const int objw = wid & 15;
    const int half = wid >> 4;
    const int cbase = half * 256 + lane;

    for (int i = tid; i < 4096; i += 1024) {
        int k = i >> 8, t4 = i & 255;
        float4 v = *(const float4*)(UV + ((size_t)(b * 16 + k)) * 1024 + t4 * 4);
        float* dst = (t4 < 128) ? (Ub + k * 512 + t4 * 4)
                                : (Vb + k * 512 + (t4 - 128) * 4);
        *(float4*)dst = v;
    }
    __syncthreads();

    const float ba0 = __ldg(&ba[0]);
    float uw[8], vw[8], war[8], Ew[8];
#pragma unroll
    for (int c = 0; c < 8; c++) {
        int t = cbase + 32 * c;
        uw[c] = Ub[objw * 512 + t];
        vw[c] = Vb[objw * 512 + t];
        war[c] = __ldg(&Wa[t]);
        Ew[c] = 0.f;
    }

#pragma unroll 1
    for (int o = 0; o < K_OBJ; o += 2) {
        float e1[8], e2[8];
        float dot1 = 0.f, dot2 = 0.f;
        const bool act1 = (o != objw);
        const bool act2 = (o + 1 != objw);
        if (act1) {
            if (o > objw) {
                const float* Vrow = Vb + o * 512;
#pragma unroll
                for (int c = 0; c < 8; c++) {
                    float x = uw[c] + Vrow[cbase + 32 * c];
                    x = (x > 0.f) ? x : (__expf(x) - 1.f);
                    e1[c] = x; dot1 += x * war[c];
                }
            } else {
                const float* Urow = Ub + o * 512;
#pragma unroll
                for (int c = 0; c < 8; c++) {
                    float x = Urow[cbase + 32 * c] + vw[c];
                    x = (x > 0.f) ? x : (__expf(x) - 1.f);
                    e1[c] = x; dot1 += x * war[c];
                }
            }
#pragma unroll
            for (int off = 16; off > 0; off >>= 1) dot1 += __shfl_xor_sync(0xffffffffu, dot1, off);
        }
        if (act2) {
            if (o + 1 > objw) {
                const float* Vrow = Vb + (o + 1) * 512;
#pragma unroll
                for (int c = 0; c < 8; c++) {
                    float x = uw[c] + Vrow[cbase + 32 * c];
                    x = (x > 0.f) ? x : (__expf(x) - 1.f);
                    e2[c] = x; dot2 += x * war[c];
                }
            } else {
                const float* Urow = Ub + (o + 1) * 512;
#pragma unroll
                for (int c = 0; c < 8; c++) {
                    float x = Urow[cbase + 32 * c] + vw[c];
                    x = (x > 0.f) ? x : (__expf(x) - 1.f);
                    e2[c] = x; dot2 += x * war[c];
                }
            }
#pragma unroll
            for (int off = 16; off > 0; off >>= 1) dot2 += __shfl_xor_sync(0xffffffffu, dot2, off);
        }
        const int buf = ((o >> 1) & 1) * 64;
        if (lane == 0) { dotp[buf + wid] = dot1; dotp[buf + 32 + wid] = dot2; }
        // pairwise sync: only warps objw and objw+16 participate (64 threads)
        asm volatile("bar.sync %0, 64;" :: "r"(objw) : "memory");
        if (act1) {
            float dsum = dot1 + dotp[buf + (wid ^ 16)];
            float att = 1.f / (1.f + __expf(-(dsum + ba0)));
#pragma unroll
            for (int c = 0; c < 8; c++) Ew[c] += att * e1[c];
        }
        if (act2) {
            float dsum = dot2 + dotp[buf + 32 + (wid ^ 16)];
            float att = 1.f / (1.f + __expf(-(dsum + ba0)));
#pragma unroll
            for (int c = 0; c < 8; c++) Ew[c] += att * e2[c];
        }
    }

    bf16* Eh = Ehi + ((size_t)b * 16 + objw) * 512;
    bf16* El = Elo + ((size_t)b * 16 + objw) * 512;
#pragma unroll
    for (int c = 0; c < 8; c++) {
        bf16 h, l; bf16split(Ew[c], h, l);
        Eh[cbase + 32 * c] = h;
        El[cbase + 32 * c] = l;
    }
}

// ---------------- host launcher ----------------
extern "C" void kernel_launch(void* const* d_in, const int* in_sizes, int n_in,
                              void* d_out, int out_size)
{
    const float* z    = (const float*)d_in[0];
    const float* h0   = (const float*)d_in[1];
    const float* W_obj= (const float*)d_in[2];
    const float* b_obj= (const float*)d_in[3];
    const float* Wih  = (const float*)d_in[4];
    const float* bih  = (const float*)d_in[5];
    const float* Whh  = (const float*)d_in[6];
    const float* bhh  = (const float*)d_in[7];
    const float* We   = (const float*)d_in[8];
    const float* be   = (const float*)d_in[9];
    const float* Wa   = (const float*)d_in[10];
    const float* ba   = (const float*)d_in[11];
    const float* Wc   = (const float*)d_in[12];
    const float* bc   = (const float*)d_in[13];
    const float* Wl   = (const float*)d_in[14];
    const float* bl   = (const float*)d_in[15];
    const float* Wsc  = (const float*)d_in[16];
    const float* bs   = (const float*)d_in[17];
    const float* Wh   = (const float*)d_in[18];
    const float* bh   = (const float*)d_in[19];

    float* out1 = (float*)d_out;
    float* out2 = out1 + (size_t)ROWS * 256;

    bf16 *p_z_hi, *p_z_lo, *p_ze_hi, *p_ze_lo;
    bf16 *p_h_hi, *p_h_lo, *p_E_hi, *p_E_lo, *p_rel_hi, *p_rel_lo;
    float *p_gi, *p_gh, *p_UV, *p_bstk, *p_buv;
    bf16 *p_Wobj_hi, *p_Wobj_lo, *p_Wih_hi, *p_Wih_lo;
    bf16 *p_WUV_hi, *p_WUV_lo, *p_WcE_hi, *p_WcE_lo, *p_Wstk_hi, *p_Wstk_lo;

    cudaGetSymbolAddress((void**)&p_z_hi,  g_z_hi);   cudaGetSymbolAddress((void**)&p_z_lo,  g_z_lo);
    cudaGetSymbolAddress((void**)&p_ze_hi, g_ze_hi);  cudaGetSymbolAddress((void**)&p_ze_lo, g_ze_lo);
    cudaGetSymbolAddress((void**)&p_h_hi,  g_h_hi);   cudaGetSymbolAddress((void**)&p_h_lo,  g_h_lo);
    cudaGetSymbolAddress((void**)&p_E_hi,  g_E_hi);   cudaGetSymbolAddress((void**)&p_E_lo,  g_E_lo);
    cudaGetSymbolAddress((void**)&p_rel_hi,g_rel_hi); cudaGetSymbolAddress((void**)&p_rel_lo,g_rel_lo);
    cudaGetSymbolAddress((void**)&p_gi, g_gi);
    cudaGetSymbolAddress((void**)&p_gh, g_gh);
    cudaGetSymbolAddress((void**)&p_UV, g_UV);
    cudaGetSymbolAddress((void**)&p_bstk, g_bstk);
    cudaGetSymbolAddress((void**)&p_buv, g_buv);
    cudaGetSymbolAddress((void**)&p_Wobj_hi, g_Wobj_hi); cudaGetSymbolAddress((void**)&p_Wobj_lo, g_Wobj_lo);
    cudaGetSymbolAddress((void**)&p_Wih_hi,  g_Wih_hi);  cudaGetSymbolAddress((void**)&p_Wih_lo,  g_Wih_lo);
    cudaGetSymbolAddress((void**)&p_WUV_hi,  g_WUV_hi);  cudaGetSymbolAddress((void**)&p_WUV_lo,  g_WUV_lo);
    cudaGetSymbolAddress((void**)&p_WcE_hi,  g_WcE_hi);  cudaGetSymbolAddress((void**)&p_WcE_lo,  g_WcE_lo);
    cudaGetSymbolAddress((void**)&p_Wstk_hi, g_Wstk_hi); cudaGetSymbolAddress((void**)&p_Wstk_lo, g_Wstk_lo);

    const int SMEM_GEMM = 2 * STG_BYTES;   // 61440
    cudaFuncSetAttribute(gemm_mma<0,6>, cudaFuncAttributeMaxDynamicSharedMemorySize, SMEM_GEMM);
    cudaFuncSetAttribute(gemm_mma<0,0>, cudaFuncAttributeMaxDynamicSharedMemorySize, SMEM_GEMM);
    cudaFuncSetAttribute(gemm_mma<0,5>, cudaFuncAttributeMaxDynamicSharedMemorySize, SMEM_GEMM);
    cudaFuncSetAttribute(gemm_mma<0,2>, cudaFuncAttributeMaxDynamicSharedMemorySize, SMEM_GEMM);

    splitprep_all<<<(N_ALL + 255) / 256, 256>>>(z, h0, W_obj, Wih, Whh,
                                                We, Wc, Wl, bl, Wsc, bs, Wh, bh, be);

    const int MB = ROWS / 128;   // 256

    // G1 (x<4: z_embed = elu(z@Wobj^T+b_obj) -> ze split) + G2b (x>=4: gh = h0@Whh^T+bhh)
    gemm_mma<0,6><<<dim3(10, MB), 256, SMEM_GEMM>>>(
        p_z_hi, p_z_lo, 128, 128, nullptr, nullptr, 0,
        p_Wobj_hi, p_Wobj_lo, b_obj, nullptr, p_ze_hi, p_ze_lo, 256, (float*)bhh, 128);

    // G2a: gi = z_embed @ Wih^T + bih  [ROWS, 384] f32
    gemm_mma<0,0><<<dim3(6, MB), 256, SMEM_GEMM>>>(
        p_ze_hi, p_ze_lo, 256, 256, nullptr, nullptr, 0,
        p_Wih_hi, p_Wih_lo, bih, p_gi, nullptr, nullptr, 384, nullptr, 256);

    // GRU gates -> h (split)
    gru_gate<<<(ROWS * 32 + 255) / 256, 256>>>(p_gi, p_gh, h0, p_h_hi, p_h_lo);

    // G3: UV = h @ W_UV^T + [be/2 | be/2]  [ROWS, 1024] f32
    gemm_mma<0,0><<<dim3(16, MB), 256, SMEM_GEMM>>>(
        p_h_hi, p_h_lo, 128, 128, nullptr, nullptr, 0,
        p_WUV_hi, p_WUV_lo, p_buv, p_UV, nullptr, nullptr, 1024, nullptr, 128);

    // pair stage -> E (split) [ROWS, 512]
    size_t psmem = (2 * 16 * 512 + 128) * sizeof(float);
    cudaFuncSetAttribute(pair_kernel, cudaFuncAttributeMaxDynamicSharedMemorySize, (int)psmem);
    pair_kernel<<<B_SZ, 1024, psmem>>>(p_UV, Wa, ba, p_E_hi, p_E_lo);

    // G4: split-K x2 in one launch (Kd=320 per half); partials -> g_gi / g_gh
    gemm_mma<0,5><<<dim3(4, MB), 256, SMEM_GEMM>>>(
        p_h_hi, p_h_lo, 128, 128, p_E_hi, p_E_lo, 512,
        p_WcE_hi, p_WcE_lo, nullptr, nullptr, nullptr, nullptr, 0, nullptr, 320);
    combine_rel<<<(ROWS * 32 + 255) / 256, 256>>>(bc);

    // G5: [loc|scale|h_out] = rel @ Wstk^T + bstk, final f32 split outputs
    gemm_mma<0,2><<<dim3(6, MB), 256, SMEM_GEMM>>>(
        p_rel_hi, p_rel_lo, 128, 128, nullptr, nullptr, 0,
        p_Wstk_hi, p_Wstk_lo, p_bstk, out1, nullptr, nullptr, 0, out2, 128);
}